// round 1
// baseline (speedup 1.0000x reference)
#include <cuda_runtime.h>
#include <cuda_bf16.h>
#include <math.h>

// ---------------- problem constants ----------------
#define LYRS 2
#define H 16
#define D 1024
#define DH 64          // D/H
#define FF 4096
#define V 32000
#define SLEN 1024
#define BS 2
#define TOK (BS*SLEN)  // 2048
#define EPS 1e-12f

// ---------------- scratch (no cudaMalloc allowed) ----------------
__device__ float g_h  [TOK*D];
__device__ float g_q  [TOK*D];
__device__ float g_k  [TOK*D];
__device__ float g_v  [TOK*D];
__device__ float g_ctx[TOK*D];
__device__ float g_tmp[TOK*D];
__device__ float g_ff [TOK*FF];

// ---------------- block reduce helper (256 threads) ----------------
__device__ __forceinline__ float block_reduce_sum256(float v, float* sbuf) {
    int tid = threadIdx.x;
    #pragma unroll
    for (int o = 16; o; o >>= 1) v += __shfl_down_sync(0xffffffffu, v, o);
    if ((tid & 31) == 0) sbuf[tid >> 5] = v;
    __syncthreads();
    if (tid < 8) {
        v = sbuf[tid];
        #pragma unroll
        for (int o = 4; o; o >>= 1) v += __shfl_down_sync(0xffu, v, o);
        if (tid == 0) sbuf[0] = v;
    }
    __syncthreads();
    float r = sbuf[0];
    __syncthreads();
    return r;
}

// ---------------- embedding + LN + mask ----------------
// one block (256 thr) per token row
__global__ void embed_ln_kernel(const int* __restrict__ x, const int* __restrict__ lengths,
                                const float* __restrict__ tok, const float* __restrict__ pos,
                                const float* __restrict__ g, const float* __restrict__ b,
                                float* __restrict__ out) {
    int row = blockIdx.x;
    int bidx = row / SLEN;
    int s = row % SLEN;
    int token = x[row];
    __shared__ float buf[D];
    __shared__ float red[8];
    int tid = threadIdx.x;

    float lsum = 0.f;
    #pragma unroll
    for (int i = 0; i < 4; i++) {
        int c = tid + i * 256;
        float val = tok[(size_t)token * D + c] + pos[(size_t)s * D + c];
        buf[c] = val;
        lsum += val;
    }
    float mean = block_reduce_sum256(lsum, red) * (1.0f / D);
    float lss = 0.f;
    #pragma unroll
    for (int i = 0; i < 4; i++) {
        int c = tid + i * 256;
        float dv = buf[c] - mean;
        lss += dv * dv;
    }
    float var = block_reduce_sum256(lss, red) * (1.0f / D);
    float rstd = rsqrtf(var + EPS);
    float mask = (s < lengths[bidx]) ? 1.0f : 0.0f;
    #pragma unroll
    for (int i = 0; i < 4; i++) {
        int c = tid + i * 256;
        out[(size_t)row * D + c] = (g[c] * (buf[c] - mean) * rstd + b[c]) * mask;
    }
}

// ---------------- residual add + LN (+ optional length mask) ----------------
// out = LN(a + delta) * (mask?)  ; safe for out == a (row-local)
__global__ void add_ln_kernel(const float* __restrict__ a, const float* __restrict__ delta,
                              const float* __restrict__ g, const float* __restrict__ b,
                              const int* __restrict__ lengths, float* __restrict__ out) {
    int row = blockIdx.x;
    int bidx = row / SLEN;
    int s = row % SLEN;
    __shared__ float buf[D];
    __shared__ float red[8];
    int tid = threadIdx.x;

    float lsum = 0.f;
    #pragma unroll
    for (int i = 0; i < 4; i++) {
        int c = tid + i * 256;
        float val = a[(size_t)row * D + c] + delta[(size_t)row * D + c];
        buf[c] = val;
        lsum += val;
    }
    float mean = block_reduce_sum256(lsum, red) * (1.0f / D);
    float lss = 0.f;
    #pragma unroll
    for (int i = 0; i < 4; i++) {
        int c = tid + i * 256;
        float dv = buf[c] - mean;
        lss += dv * dv;
    }
    float var = block_reduce_sum256(lss, red) * (1.0f / D);
    float rstd = rsqrtf(var + EPS);
    float mask = 1.0f;
    if (lengths) mask = (s < lengths[bidx]) ? 1.0f : 0.0f;
    #pragma unroll
    for (int i = 0; i < 4; i++) {
        int c = tid + i * 256;
        out[(size_t)row * D + c] = (g[c] * (buf[c] - mean) * rstd + b[c]) * mask;
    }
}

// ---------------- SGEMM: C[M,N] = A[M,K] @ B[K,N] + bias, optional erf-GELU ----
// BM=BN=128, BK=16, 256 threads, 8x8 per thread. Requires M%128==0, N%128==0, K%16==0.
#define BM 128
#define BN 128
#define BK 16
#define TM 8
#define TN 8

__global__ __launch_bounds__(256) void sgemm_kernel(
    const float* __restrict__ A, const float* __restrict__ B,
    const float* __restrict__ bias, float* __restrict__ C,
    int M, int N, int K, int act /*0=none,1=gelu*/) {

    const int bx = blockIdx.x;   // N tile
    const int by = blockIdx.y;   // M tile
    const int tid = threadIdx.x;
    const int tx = tid & 15;     // 0..15 -> column group
    const int ty = tid >> 4;     // 0..15 -> row group

    const float* Ab = A + (size_t)by * BM * K;
    const float* Bb = B + (size_t)bx * BN;
    float* Cb = C + (size_t)by * BM * N + (size_t)bx * BN;

    __shared__ float As[BK][BM];
    __shared__ float Bs[BK][BN];

    float acc[TM][TN];
    #pragma unroll
    for (int i = 0; i < TM; i++)
        #pragma unroll
        for (int j = 0; j < TN; j++) acc[i][j] = 0.f;

    for (int k0 = 0; k0 < K; k0 += BK) {
        #pragma unroll
        for (int ld = 0; ld < 2; ld++) {
            int idx = tid + ld * 256;
            // A: 128 rows x 4 float4 per row
            int arow = idx >> 2;
            int ak = (idx & 3) * 4;
            float4 av = *(const float4*)(Ab + (size_t)arow * K + k0 + ak);
            As[ak + 0][arow] = av.x;
            As[ak + 1][arow] = av.y;
            As[ak + 2][arow] = av.z;
            As[ak + 3][arow] = av.w;
            // B: 16 rows x 32 float4 per row
            int brow = idx >> 5;
            int bcol = (idx & 31) * 4;
            *(float4*)(&Bs[brow][bcol]) = *(const float4*)(Bb + (size_t)(k0 + brow) * N + bcol);
        }
        __syncthreads();
        #pragma unroll
        for (int kk = 0; kk < BK; kk++) {
            float af[TM], bf[TN];
            #pragma unroll
            for (int i = 0; i < TM; i++) af[i] = As[kk][ty * TM + i];
            #pragma unroll
            for (int j = 0; j < TN; j++) bf[j] = Bs[kk][tx * TN + j];
            #pragma unroll
            for (int i = 0; i < TM; i++)
                #pragma unroll
                for (int j = 0; j < TN; j++)
                    acc[i][j] = fmaf(af[i], bf[j], acc[i][j]);
        }
        __syncthreads();
    }

    #pragma unroll
    for (int i = 0; i < TM; i++) {
        int r = ty * TM + i;
        #pragma unroll
        for (int j = 0; j < TN; j++) {
            int c = tx * TN + j;
            float val = acc[i][j] + bias[(size_t)bx * BN + c];
            if (act == 1) val = 0.5f * val * (1.0f + erff(val * 0.70710678118654752f));
            Cb[(size_t)r * N + c] = val;
        }
    }
}

// ---------------- causal attention: one block per (q, head, batch) ----------
__global__ void attn_kernel(const float* __restrict__ q, const float* __restrict__ k,
                            const float* __restrict__ v, float* __restrict__ ctx) {
    const int qpos = blockIdx.x;
    const int hd = blockIdx.y;
    const int bb = blockIdx.z;
    const int tid = threadIdx.x;   // 128 threads
    const int nk = qpos + 1;

    __shared__ float sq[DH];
    __shared__ float sc[SLEN];
    __shared__ float red[128];

    const float* qrow = q + ((size_t)(bb * SLEN + qpos)) * D + hd * DH;
    if (tid < DH) sq[tid] = qrow[tid] * 0.125f;   // 1/sqrt(64)
    __syncthreads();

    const float* kbase = k + ((size_t)bb * SLEN) * D + hd * DH;
    for (int key = tid; key < nk; key += 128) {
        const float* kr = kbase + (size_t)key * D;
        float s = 0.f;
        #pragma unroll
        for (int d = 0; d < DH; d++) s = fmaf(sq[d], kr[d], s);
        sc[key] = s;
    }
    __syncthreads();

    // softmax: max
    float mx = -1e30f;
    for (int key = tid; key < nk; key += 128) mx = fmaxf(mx, sc[key]);
    red[tid] = mx; __syncthreads();
    #pragma unroll
    for (int off = 64; off; off >>= 1) {
        if (tid < off) red[tid] = fmaxf(red[tid], red[tid + off]);
        __syncthreads();
    }
    mx = red[0]; __syncthreads();

    // exp + sum
    float lsum = 0.f;
    for (int key = tid; key < nk; key += 128) {
        float e = expf(sc[key] - mx);
        sc[key] = e;
        lsum += e;
    }
    red[tid] = lsum; __syncthreads();
    #pragma unroll
    for (int off = 64; off; off >>= 1) {
        if (tid < off) red[tid] += red[tid + off];
        __syncthreads();
    }
    float inv = 1.0f / red[0];
    __syncthreads();

    // ctx = softmax @ V ; 2 halves of the block cover even/odd keys
    const int d = tid & 63;
    const int half = tid >> 6;
    const float* vbase = v + ((size_t)bb * SLEN) * D + hd * DH + d;
    float acc = 0.f;
    for (int key = half; key < nk; key += 2)
        acc = fmaf(sc[key], vbase[(size_t)key * D], acc);
    red[tid] = acc; __syncthreads();
    if (tid < 64)
        ctx[((size_t)(bb * SLEN + qpos)) * D + hd * DH + tid] = (red[tid] + red[tid + 64]) * inv;
}

// ---------------- launcher ----------------
extern "C" void kernel_launch(void* const* d_in, const int* in_sizes, int n_in,
                              void* d_out, int out_size) {
    const int*   x        = (const int*)  d_in[0];
    const int*   lengths  = (const int*)  d_in[1];
    const float* tok_emb  = (const float*)d_in[2];
    const float* pos_emb  = (const float*)d_in[3];
    const float* ln_emb_g = (const float*)d_in[4];
    const float* ln_emb_b = (const float*)d_in[5];
    const float* Wq = (const float*)d_in[6];  const float* bq = (const float*)d_in[7];
    const float* Wk = (const float*)d_in[8];  const float* bk = (const float*)d_in[9];
    const float* Wv = (const float*)d_in[10]; const float* bv = (const float*)d_in[11];
    const float* Wo = (const float*)d_in[12]; const float* bo = (const float*)d_in[13];
    const float* ln1_g = (const float*)d_in[14]; const float* ln1_b = (const float*)d_in[15];
    const float* W1 = (const float*)d_in[16]; const float* b1 = (const float*)d_in[17];
    const float* W2 = (const float*)d_in[18]; const float* b2 = (const float*)d_in[19];
    const float* ln2_g = (const float*)d_in[20]; const float* ln2_b = (const float*)d_in[21];
    const float* projW = (const float*)d_in[22]; const float* projb = (const float*)d_in[23];
    float* out = (float*)d_out;

    float *h, *q, *k, *v, *ctx, *tmp, *ff;
    cudaGetSymbolAddress((void**)&h,   g_h);
    cudaGetSymbolAddress((void**)&q,   g_q);
    cudaGetSymbolAddress((void**)&k,   g_k);
    cudaGetSymbolAddress((void**)&v,   g_v);
    cudaGetSymbolAddress((void**)&ctx, g_ctx);
    cudaGetSymbolAddress((void**)&tmp, g_tmp);
    cudaGetSymbolAddress((void**)&ff,  g_ff);

    embed_ln_kernel<<<TOK, 256>>>(x, lengths, tok_emb, pos_emb, ln_emb_g, ln_emb_b, h);

    for (int i = 0; i < LYRS; i++) {
        const size_t wOff = (size_t)i * D * D;
        sgemm_kernel<<<dim3(D / BN, TOK / BM), 256>>>(h, Wq + wOff, bq + (size_t)i * D, q, TOK, D, D, 0);
        sgemm_kernel<<<dim3(D / BN, TOK / BM), 256>>>(h, Wk + wOff, bk + (size_t)i * D, k, TOK, D, D, 0);
        sgemm_kernel<<<dim3(D / BN, TOK / BM), 256>>>(h, Wv + wOff, bv + (size_t)i * D, v, TOK, D, D, 0);

        attn_kernel<<<dim3(SLEN, H, BS), 128>>>(q, k, v, ctx);

        sgemm_kernel<<<dim3(D / BN, TOK / BM), 256>>>(ctx, Wo + wOff, bo + (size_t)i * D, tmp, TOK, D, D, 0);
        add_ln_kernel<<<TOK, 256>>>(h, tmp, ln1_g + (size_t)i * D, ln1_b + (size_t)i * D, nullptr, h);

        sgemm_kernel<<<dim3(FF / BN, TOK / BM), 256>>>(h, W1 + (size_t)i * D * FF, b1 + (size_t)i * FF, ff, TOK, FF, D, 1);
        sgemm_kernel<<<dim3(D / BN, TOK / BM), 256>>>(ff, W2 + (size_t)i * FF * D, b2 + (size_t)i * D, tmp, TOK, D, FF, 0);
        add_ln_kernel<<<TOK, 256>>>(h, tmp, ln2_g + (size_t)i * D, ln2_b + (size_t)i * D, lengths, h);
    }

    sgemm_kernel<<<dim3(V / BN, TOK / BM), 256>>>(h, projW, projb, out, TOK, V, D, 0);
}

// round 2
// speedup vs baseline: 1.0006x; 1.0006x over previous
#include <cuda_runtime.h>
#include <cuda_bf16.h>
#include <math.h>

// ---------------- problem constants ----------------
#define LYRS 2
#define H 16
#define D 1024
#define DH 64          // D/H
#define FF 4096
#define V 32000
#define SLEN 1024
#define BS 2
#define TOK (BS*SLEN)  // 2048
#define EPS 1e-12f

// ---------------- scratch (no cudaMalloc allowed) ----------------
__device__ float g_h  [TOK*D];
__device__ float g_q  [TOK*D];
__device__ float g_k  [TOK*D];
__device__ float g_v  [TOK*D];
__device__ float g_ctx[TOK*D];
__device__ float g_tmp[TOK*D];
__device__ float g_ff [TOK*FF];

// ---------------- block reduce helper (256 threads) ----------------
__device__ __forceinline__ float block_reduce_sum256(float v, float* sbuf) {
    int tid = threadIdx.x;
    #pragma unroll
    for (int o = 16; o; o >>= 1) v += __shfl_down_sync(0xffffffffu, v, o);
    if ((tid & 31) == 0) sbuf[tid >> 5] = v;
    __syncthreads();
    if (tid < 8) {
        v = sbuf[tid];
        #pragma unroll
        for (int o = 4; o; o >>= 1) v += __shfl_down_sync(0xffu, v, o);
        if (tid == 0) sbuf[0] = v;
    }
    __syncthreads();
    float r = sbuf[0];
    __syncthreads();
    return r;
}

// ---------------- embedding + LN + mask ----------------
// one block (256 thr) per token row
__global__ void embed_ln_kernel(const int* __restrict__ x, const int* __restrict__ lengths,
                                const float* __restrict__ tok, const float* __restrict__ pos,
                                const float* __restrict__ g, const float* __restrict__ b,
                                float* __restrict__ out) {
    int row = blockIdx.x;
    int bidx = row / SLEN;
    int s = row % SLEN;
    int token = x[row];
    __shared__ float buf[D];
    __shared__ float red[8];
    int tid = threadIdx.x;

    float lsum = 0.f;
    #pragma unroll
    for (int i = 0; i < 4; i++) {
        int c = tid + i * 256;
        float val = tok[(size_t)token * D + c] + pos[(size_t)s * D + c];
        buf[c] = val;
        lsum += val;
    }
    float mean = block_reduce_sum256(lsum, red) * (1.0f / D);
    float lss = 0.f;
    #pragma unroll
    for (int i = 0; i < 4; i++) {
        int c = tid + i * 256;
        float dv = buf[c] - mean;
        lss += dv * dv;
    }
    float var = block_reduce_sum256(lss, red) * (1.0f / D);
    float rstd = rsqrtf(var + EPS);
    float mask = (s < lengths[bidx]) ? 1.0f : 0.0f;
    #pragma unroll
    for (int i = 0; i < 4; i++) {
        int c = tid + i * 256;
        out[(size_t)row * D + c] = (g[c] * (buf[c] - mean) * rstd + b[c]) * mask;
    }
}

// ---------------- residual add + LN (+ optional length mask) ----------------
// out = LN(a + delta) * (mask?)  ; safe for out == a (row-local)
__global__ void add_ln_kernel(const float* __restrict__ a, const float* __restrict__ delta,
                              const float* __restrict__ g, const float* __restrict__ b,
                              const int* __restrict__ lengths, float* __restrict__ out) {
    int row = blockIdx.x;
    int bidx = row / SLEN;
    int s = row % SLEN;
    __shared__ float buf[D];
    __shared__ float red[8];
    int tid = threadIdx.x;

    float lsum = 0.f;
    #pragma unroll
    for (int i = 0; i < 4; i++) {
        int c = tid + i * 256;
        float val = a[(size_t)row * D + c] + delta[(size_t)row * D + c];
        buf[c] = val;
        lsum += val;
    }
    float mean = block_reduce_sum256(lsum, red) * (1.0f / D);
    float lss = 0.f;
    #pragma unroll
    for (int i = 0; i < 4; i++) {
        int c = tid + i * 256;
        float dv = buf[c] - mean;
        lss += dv * dv;
    }
    float var = block_reduce_sum256(lss, red) * (1.0f / D);
    float rstd = rsqrtf(var + EPS);
    float mask = 1.0f;
    if (lengths) mask = (s < lengths[bidx]) ? 1.0f : 0.0f;
    #pragma unroll
    for (int i = 0; i < 4; i++) {
        int c = tid + i * 256;
        out[(size_t)row * D + c] = (g[c] * (buf[c] - mean) * rstd + b[c]) * mask;
    }
}

// ---------------- SGEMM: C[M,N] = A[M,K] @ B[K,N] + bias, optional erf-GELU ----
// BM=BN=128, BK=16, 256 threads, 8x8 per thread. Requires M%128==0, N%128==0, K%16==0.
#define BM 128
#define BN 128
#define BK 16
#define TM 8
#define TN 8

__global__ __launch_bounds__(256) void sgemm_kernel(
    const float* __restrict__ A, const float* __restrict__ B,
    const float* __restrict__ bias, float* __restrict__ C,
    int M, int N, int K, int act /*0=none,1=gelu*/) {

    const int bx = blockIdx.x;   // N tile
    const int by = blockIdx.y;   // M tile
    const int tid = threadIdx.x;
    const int tx = tid & 15;     // 0..15 -> column group
    const int ty = tid >> 4;     // 0..15 -> row group

    const float* Ab = A + (size_t)by * BM * K;
    const float* Bb = B + (size_t)bx * BN;
    float* Cb = C + (size_t)by * BM * N + (size_t)bx * BN;

    __shared__ float As[BK][BM];
    __shared__ float Bs[BK][BN];

    float acc[TM][TN];
    #pragma unroll
    for (int i = 0; i < TM; i++)
        #pragma unroll
        for (int j = 0; j < TN; j++) acc[i][j] = 0.f;

    for (int k0 = 0; k0 < K; k0 += BK) {
        #pragma unroll
        for (int ld = 0; ld < 2; ld++) {
            int idx = tid + ld * 256;
            // A: 128 rows x 4 float4 per row
            int arow = idx >> 2;
            int ak = (idx & 3) * 4;
            float4 av = *(const float4*)(Ab + (size_t)arow * K + k0 + ak);
            As[ak + 0][arow] = av.x;
            As[ak + 1][arow] = av.y;
            As[ak + 2][arow] = av.z;
            As[ak + 3][arow] = av.w;
            // B: 16 rows x 32 float4 per row
            int brow = idx >> 5;
            int bcol = (idx & 31) * 4;
            *(float4*)(&Bs[brow][bcol]) = *(const float4*)(Bb + (size_t)(k0 + brow) * N + bcol);
        }
        __syncthreads();
        #pragma unroll
        for (int kk = 0; kk < BK; kk++) {
            float af[TM], bf[TN];
            #pragma unroll
            for (int i = 0; i < TM; i++) af[i] = As[kk][ty * TM + i];
            #pragma unroll
            for (int j = 0; j < TN; j++) bf[j] = Bs[kk][tx * TN + j];
            #pragma unroll
            for (int i = 0; i < TM; i++)
                #pragma unroll
                for (int j = 0; j < TN; j++)
                    acc[i][j] = fmaf(af[i], bf[j], acc[i][j]);
        }
        __syncthreads();
    }

    #pragma unroll
    for (int i = 0; i < TM; i++) {
        int r = ty * TM + i;
        #pragma unroll
        for (int j = 0; j < TN; j++) {
            int c = tx * TN + j;
            float val = acc[i][j] + bias[(size_t)bx * BN + c];
            if (act == 1) val = 0.5f * val * (1.0f + erff(val * 0.70710678118654752f));
            Cb[(size_t)r * N + c] = val;
        }
    }
}

// ---------------- causal attention: one block per (q, head, batch) ----------
__global__ void attn_kernel(const float* __restrict__ q, const float* __restrict__ k,
                            const float* __restrict__ v, float* __restrict__ ctx) {
    const int qpos = blockIdx.x;
    const int hd = blockIdx.y;
    const int bb = blockIdx.z;
    const int tid = threadIdx.x;   // 128 threads
    const int nk = qpos + 1;

    __shared__ float sq[DH];
    __shared__ float sc[SLEN];
    __shared__ float red[128];

    const float* qrow = q + ((size_t)(bb * SLEN + qpos)) * D + hd * DH;
    if (tid < DH) sq[tid] = qrow[tid] * 0.125f;   // 1/sqrt(64)
    __syncthreads();

    const float* kbase = k + ((size_t)bb * SLEN) * D + hd * DH;
    for (int key = tid; key < nk; key += 128) {
        const float* kr = kbase + (size_t)key * D;
        float s = 0.f;
        #pragma unroll
        for (int d = 0; d < DH; d++) s = fmaf(sq[d], kr[d], s);
        sc[key] = s;
    }
    __syncthreads();

    // softmax: max
    float mx = -1e30f;
    for (int key = tid; key < nk; key += 128) mx = fmaxf(mx, sc[key]);
    red[tid] = mx; __syncthreads();
    #pragma unroll
    for (int off = 64; off; off >>= 1) {
        if (tid < off) red[tid] = fmaxf(red[tid], red[tid + off]);
        __syncthreads();
    }
    mx = red[0]; __syncthreads();

    // exp + sum
    float lsum = 0.f;
    for (int key = tid; key < nk; key += 128) {
        float e = expf(sc[key] - mx);
        sc[key] = e;
        lsum += e;
    }
    red[tid] = lsum; __syncthreads();
    #pragma unroll
    for (int off = 64; off; off >>= 1) {
        if (tid < off) red[tid] += red[tid + off];
        __syncthreads();
    }
    float inv = 1.0f / red[0];
    __syncthreads();

    // ctx = softmax @ V ; 2 halves of the block cover even/odd keys
    const int d = tid & 63;
    const int half = tid >> 6;
    const float* vbase = v + ((size_t)bb * SLEN) * D + hd * DH + d;
    float acc = 0.f;
    for (int key = half; key < nk; key += 2)
        acc = fmaf(sc[key], vbase[(size_t)key * D], acc);
    red[tid] = acc; __syncthreads();
    if (tid < 64)
        ctx[((size_t)(bb * SLEN + qpos)) * D + hd * DH + tid] = (red[tid] + red[tid + 64]) * inv;
}

// ---------------- launcher ----------------
extern "C" void kernel_launch(void* const* d_in, const int* in_sizes, int n_in,
                              void* d_out, int out_size) {
    const int*   x        = (const int*)  d_in[0];
    const int*   lengths  = (const int*)  d_in[1];
    const float* tok_emb  = (const float*)d_in[2];
    const float* pos_emb  = (const float*)d_in[3];
    const float* ln_emb_g = (const float*)d_in[4];
    const float* ln_emb_b = (const float*)d_in[5];
    const float* Wq = (const float*)d_in[6];  const float* bq = (const float*)d_in[7];
    const float* Wk = (const float*)d_in[8];  const float* bk = (const float*)d_in[9];
    const float* Wv = (const float*)d_in[10]; const float* bv = (const float*)d_in[11];
    const float* Wo = (const float*)d_in[12]; const float* bo = (const float*)d_in[13];
    const float* ln1_g = (const float*)d_in[14]; const float* ln1_b = (const float*)d_in[15];
    const float* W1 = (const float*)d_in[16]; const float* b1 = (const float*)d_in[17];
    const float* W2 = (const float*)d_in[18]; const float* b2 = (const float*)d_in[19];
    const float* ln2_g = (const float*)d_in[20]; const float* ln2_b = (const float*)d_in[21];
    const float* projW = (const float*)d_in[22]; const float* projb = (const float*)d_in[23];
    float* out = (float*)d_out;

    float *h, *q, *k, *v, *ctx, *tmp, *ff;
    cudaGetSymbolAddress((void**)&h,   g_h);
    cudaGetSymbolAddress((void**)&q,   g_q);
    cudaGetSymbolAddress((void**)&k,   g_k);
    cudaGetSymbolAddress((void**)&v,   g_v);
    cudaGetSymbolAddress((void**)&ctx, g_ctx);
    cudaGetSymbolAddress((void**)&tmp, g_tmp);
    cudaGetSymbolAddress((void**)&ff,  g_ff);

    embed_ln_kernel<<<TOK, 256>>>(x, lengths, tok_emb, pos_emb, ln_emb_g, ln_emb_b, h);

    for (int i = 0; i < LYRS; i++) {
        const size_t wOff = (size_t)i * D * D;
        sgemm_kernel<<<dim3(D / BN, TOK / BM), 256>>>(h, Wq + wOff, bq + (size_t)i * D, q, TOK, D, D, 0);
        sgemm_kernel<<<dim3(D / BN, TOK / BM), 256>>>(h, Wk + wOff, bk + (size_t)i * D, k, TOK, D, D, 0);
        sgemm_kernel<<<dim3(D / BN, TOK / BM), 256>>>(h, Wv + wOff, bv + (size_t)i * D, v, TOK, D, D, 0);

        attn_kernel<<<dim3(SLEN, H, BS), 128>>>(q, k, v, ctx);

        sgemm_kernel<<<dim3(D / BN, TOK / BM), 256>>>(ctx, Wo + wOff, bo + (size_t)i * D, tmp, TOK, D, D, 0);
        add_ln_kernel<<<TOK, 256>>>(h, tmp, ln1_g + (size_t)i * D, ln1_b + (size_t)i * D, nullptr, h);

        sgemm_kernel<<<dim3(FF / BN, TOK / BM), 256>>>(h, W1 + (size_t)i * D * FF, b1 + (size_t)i * FF, ff, TOK, FF, D, 1);
        sgemm_kernel<<<dim3(D / BN, TOK / BM), 256>>>(ff, W2 + (size_t)i * FF * D, b2 + (size_t)i * D, tmp, TOK, D, FF, 0);
        add_ln_kernel<<<TOK, 256>>>(h, tmp, ln2_g + (size_t)i * D, ln2_b + (size_t)i * D, lengths, h);
    }

    sgemm_kernel<<<dim3(V / BN, TOK / BM), 256>>>(h, projW, projb, out, TOK, V, D, 0);
}

// round 4
// speedup vs baseline: 3.1672x; 3.1654x over previous
#include <cuda_runtime.h>
#include <cuda_bf16.h>
#include <math.h>
#include <stdint.h>

#define LYRS 2
#define H 16
#define D 1024
#define DH 64
#define FF 4096
#define V 32000
#define SLEN 1024
#define BS 2
#define TOK (BS*SLEN)
#define EPS 1e-12f
#define K3D (3*D)
#define K3F (3*FF)

// GEMM tiling
#define BKC 64                 // K per stage (bf16 elems)
#define ROWB 144               // padded SMEM row bytes (64*2 data + 16 pad)
#define TILEB (128*ROWB)       // one 128-row tile
#define STGSZ (2*TILEB)        // A+B per stage
#define NSTG 3

// ---------------- scratch ----------------
__device__ float g_h  [TOK*D];
__device__ float g_qkv[TOK*K3D];
__device__ float g_ctx[TOK*D];
__device__ float g_tmp[TOK*D];
__device__ float g_ff [TOK*FF];
__device__ float g_bqkv[LYRS*K3D];
__device__ __align__(256) __nv_bfloat16 g_a3 [TOK*K3F];
__device__ __align__(256) __nv_bfloat16 g_wqkv[LYRS*(size_t)K3D*K3D];
__device__ __align__(256) __nv_bfloat16 g_wo  [LYRS*(size_t)D*K3D];
__device__ __align__(256) __nv_bfloat16 g_w1  [LYRS*(size_t)FF*K3D];
__device__ __align__(256) __nv_bfloat16 g_w2  [LYRS*(size_t)D*K3F];
__device__ __align__(256) __nv_bfloat16 g_wp  [(size_t)V*K3D];

// ---------------- helpers ----------------
__device__ __forceinline__ uint32_t s2u(const void* p) {
    uint32_t a;
    asm("{ .reg .u64 t; cvta.to.shared.u64 t, %1; cvt.u32.u64 %0, t; }" : "=r"(a) : "l"(p));
    return a;
}
__device__ __forceinline__ void cpa16(uint32_t dst, const void* src) {
    asm volatile("cp.async.cg.shared.global [%0], [%1], 16;" :: "r"(dst), "l"(src));
}
__device__ __forceinline__ void ldm4(uint32_t (&r)[4], uint32_t addr) {
    asm volatile("ldmatrix.sync.aligned.m8n8.x4.shared.b16 {%0,%1,%2,%3}, [%4];"
                 : "=r"(r[0]), "=r"(r[1]), "=r"(r[2]), "=r"(r[3]) : "r"(addr));
}
__device__ __forceinline__ void mma16816(float (&c)[4], const uint32_t a0, const uint32_t a1,
                                         const uint32_t a2, const uint32_t a3,
                                         const uint32_t b0, const uint32_t b1) {
    asm volatile("mma.sync.aligned.m16n8k16.row.col.f32.bf16.bf16.f32 "
                 "{%0,%1,%2,%3}, {%4,%5,%6,%7}, {%8,%9}, {%0,%1,%2,%3};"
                 : "+f"(c[0]), "+f"(c[1]), "+f"(c[2]), "+f"(c[3])
                 : "r"(a0), "r"(a1), "r"(a2), "r"(a3), "r"(b0), "r"(b1));
}

// ---------------- bf16x3 conversions ----------------
__global__ void convert_act(const float* __restrict__ in, __nv_bfloat16* __restrict__ out, int Kd) {
    int idx = blockIdx.x * 256 + threadIdx.x;
    if (idx >= TOK * (Kd / 2)) return;
    int m = idx / (Kd / 2), k2 = idx % (Kd / 2);
    float2 v = ((const float2*)in)[idx];
    __nv_bfloat162 hi, lo;
    hi.x = __float2bfloat16(v.x); hi.y = __float2bfloat16(v.y);
    lo.x = __float2bfloat16(v.x - __bfloat162float(hi.x));
    lo.y = __float2bfloat16(v.y - __bfloat162float(hi.y));
    __nv_bfloat162* o = (__nv_bfloat162*)(out + (size_t)m * 3 * Kd);
    o[k2] = hi; o[Kd / 2 + k2] = hi; o[Kd + k2] = lo;
}
// W[K,N] f32 -> rows (rowOff+n): [hi | lo | hi], row stride ld3 = 3K
__global__ void convert_w(const float* __restrict__ W, __nv_bfloat16* __restrict__ out,
                          int K, int N, int rowOff, int ld3) {
    __shared__ float t[32][33];
    int k0 = blockIdx.x * 32, n0 = blockIdx.y * 32;
    int tx = threadIdx.x & 31, ty = threadIdx.x >> 5;
    #pragma unroll
    for (int i = 0; i < 4; i++)
        t[ty + i * 8][tx] = W[(size_t)(k0 + ty + i * 8) * N + n0 + tx];
    __syncthreads();
    #pragma unroll
    for (int i = 0; i < 4; i++) {
        int n = n0 + ty + i * 8, k = k0 + tx;
        float v = t[tx][ty + i * 8];
        __nv_bfloat16 hi = __float2bfloat16(v);
        __nv_bfloat16 lo = __float2bfloat16(v - __bfloat162float(hi));
        __nv_bfloat16* o = out + (size_t)(rowOff + n) * ld3;
        o[k] = hi; o[K + k] = lo; o[2 * K + k] = hi;
    }
}
__global__ void concat_bias(const float* __restrict__ a, const float* __restrict__ b,
                            const float* __restrict__ c, float* __restrict__ o) {
    int i = blockIdx.x * 256 + threadIdx.x;
    if (i < D) { o[i] = a[i]; o[D + i] = b[i]; o[2 * D + i] = c[i]; }
}

// ---------------- mma.sync GEMM: C[2048,ldc] = A[M,Kp] @ B[N,Kp]^T + bias ----
// CTA tile 128x128x64, 8 warps (4 M x 2 N), warp tile 32x64, 3-stage cp.async.
__global__ void __launch_bounds__(256, 1) gemm_kernel(
    const __nv_bfloat16* __restrict__ A, const __nv_bfloat16* __restrict__ B,
    const float* __restrict__ bias, float* __restrict__ C, int Kp, int ldc, int act)
{
    extern __shared__ __align__(128) char smem[];
    const int tid = threadIdx.x, wid = tid >> 5, lane = tid & 31;
    const int wm = wid & 3, wn = wid >> 2;
    const int m0 = blockIdx.x * 128, n0 = blockIdx.y * 128;
    const uint32_t sb = s2u(smem);
    const size_t Ks = (size_t)Kp;

    float acc[2][8][4];
    #pragma unroll
    for (int mi = 0; mi < 2; mi++)
        #pragma unroll
        for (int ni = 0; ni < 8; ni++)
            #pragma unroll
            for (int j = 0; j < 4; j++) acc[mi][ni][j] = 0.f;

    const int nch = Kp / BKC;

    auto load_chunk = [&](int c) {
        uint32_t base = sb + (c % NSTG) * STGSZ;
        const __nv_bfloat16* Ag = A + (size_t)m0 * Ks + c * BKC;
        const __nv_bfloat16* Bg = B + (size_t)n0 * Ks + c * BKC;
        #pragma unroll
        for (int j = 0; j < 4; j++) {
            int idx = tid + j * 256;
            int r = idx >> 3, ch = idx & 7;
            cpa16(base + r * ROWB + ch * 16, (const char*)(Ag + (size_t)r * Ks) + ch * 16);
        }
        #pragma unroll
        for (int j = 0; j < 4; j++) {
            int idx = tid + j * 256;
            int r = idx >> 3, ch = idx & 7;
            cpa16(base + TILEB + r * ROWB + ch * 16, (const char*)(Bg + (size_t)r * Ks) + ch * 16);
        }
    };

    load_chunk(0);
    asm volatile("cp.async.commit_group;" ::: "memory");
    load_chunk(1);
    asm volatile("cp.async.commit_group;" ::: "memory");

    // per-lane ldmatrix base offsets (quadrant order: m0k0, m8k0, m0k8, m8k8)
    const int lq = lane & 7, lh = (lane >> 3) & 1, lk = lane >> 4;
    const uint32_t aOff = (uint32_t)((wm * 32 + lh * 8 + lq) * ROWB + lk * 16);
    const uint32_t bOff = (uint32_t)(TILEB + (wn * 64 + lh * 8 + lq) * ROWB + lk * 16);

    for (int c = 0; c < nch; c++) {
        asm volatile("cp.async.wait_group 1;" ::: "memory");
        __syncthreads();
        if (c + 2 < nch) load_chunk(c + 2);
        asm volatile("cp.async.commit_group;" ::: "memory");

        uint32_t stg = sb + (c % NSTG) * STGSZ;
        #pragma unroll
        for (int ks = 0; ks < BKC / 16; ks++) {
            uint32_t a0[4], a1[4], bf[4][4];
            ldm4(a0, stg + aOff + ks * 32);
            ldm4(a1, stg + aOff + 16 * ROWB + ks * 32);
            #pragma unroll
            for (int nt = 0; nt < 4; nt++)
                ldm4(bf[nt], stg + bOff + nt * 16 * ROWB + ks * 32);
            #pragma unroll
            for (int ni = 0; ni < 8; ni++) {
                uint32_t b0 = bf[ni >> 1][ni & 1], b1 = bf[ni >> 1][(ni & 1) + 2];
                mma16816(acc[0][ni], a0[0], a0[1], a0[2], a0[3], b0, b1);
                mma16816(acc[1][ni], a1[0], a1[1], a1[2], a1[3], b0, b1);
            }
        }
        __syncthreads();
    }

    // epilogue: bias + optional gelu, float2 stores
    const int r0 = lane >> 2, cp = (lane & 3) * 2;
    #pragma unroll
    for (int mi = 0; mi < 2; mi++) {
        #pragma unroll
        for (int ni = 0; ni < 8; ni++) {
            int col = n0 + wn * 64 + ni * 8 + cp;
            float bb0 = bias[col], bb1 = bias[col + 1];
            #pragma unroll
            for (int half = 0; half < 2; half++) {
                int row = m0 + wm * 32 + mi * 16 + r0 + half * 8;
                float v0 = acc[mi][ni][half * 2 + 0] + bb0;
                float v1 = acc[mi][ni][half * 2 + 1] + bb1;
                if (act) {
                    v0 = 0.5f * v0 * (1.0f + erff(v0 * 0.70710678118654752f));
                    v1 = 0.5f * v1 * (1.0f + erff(v1 * 0.70710678118654752f));
                }
                float2 o; o.x = v0; o.y = v1;
                *(float2*)(C + (size_t)row * ldc + col) = o;
            }
        }
    }
}

// ---------------- LayerNorm ----------------
__device__ __forceinline__ float brsum(float v, float* sbuf) {
    int tid = threadIdx.x;
    #pragma unroll
    for (int o = 16; o; o >>= 1) v += __shfl_down_sync(0xffffffffu, v, o);
    if ((tid & 31) == 0) sbuf[tid >> 5] = v;
    __syncthreads();
    if (tid < 8) {
        v = sbuf[tid];
        #pragma unroll
        for (int o = 4; o; o >>= 1) v += __shfl_down_sync(0xffu, v, o);
        if (tid == 0) sbuf[0] = v;
    }
    __syncthreads();
    float r = sbuf[0];
    __syncthreads();
    return r;
}
__global__ void embed_ln_kernel(const int* __restrict__ x, const int* __restrict__ len,
                                const float* __restrict__ tok, const float* __restrict__ pos,
                                const float* __restrict__ g, const float* __restrict__ b,
                                float* __restrict__ out) {
    int row = blockIdx.x, bi = row / SLEN, s = row % SLEN, token = x[row], tid = threadIdx.x;
    __shared__ float buf[D]; __shared__ float red[8];
    float ls = 0.f;
    #pragma unroll
    for (int i = 0; i < 4; i++) {
        int c = tid + i * 256;
        float v = tok[(size_t)token * D + c] + pos[(size_t)s * D + c];
        buf[c] = v; ls += v;
    }
    float mean = brsum(ls, red) * (1.0f / D), ss = 0.f;
    #pragma unroll
    for (int i = 0; i < 4; i++) { float d = buf[tid + i * 256] - mean; ss += d * d; }
    float rstd = rsqrtf(brsum(ss, red) * (1.0f / D) + EPS);
    float mask = (s < len[bi]) ? 1.0f : 0.0f;
    #pragma unroll
    for (int i = 0; i < 4; i++) {
        int c = tid + i * 256;
        out[(size_t)row * D + c] = (g[c] * (buf[c] - mean) * rstd + b[c]) * mask;
    }
}
__global__ void add_ln_kernel(const float* __restrict__ a, const float* __restrict__ dl,
                              const float* __restrict__ g, const float* __restrict__ b,
                              const int* __restrict__ len, float* __restrict__ out) {
    int row = blockIdx.x, bi = row / SLEN, s = row % SLEN, tid = threadIdx.x;
    __shared__ float buf[D]; __shared__ float red[8];
    float ls = 0.f;
    #pragma unroll
    for (int i = 0; i < 4; i++) {
        int c = tid + i * 256;
        float v = a[(size_t)row * D + c] + dl[(size_t)row * D + c];
        buf[c] = v; ls += v;
    }
    float mean = brsum(ls, red) * (1.0f / D), ss = 0.f;
    #pragma unroll
    for (int i = 0; i < 4; i++) { float d = buf[tid + i * 256] - mean; ss += d * d; }
    float rstd = rsqrtf(brsum(ss, red) * (1.0f / D) + EPS);
    float mask = len ? ((s < len[bi]) ? 1.0f : 0.0f) : 1.0f;
    #pragma unroll
    for (int i = 0; i < 4; i++) {
        int c = tid + i * 256;
        out[(size_t)row * D + c] = (g[c] * (buf[c] - mean) * rstd + b[c]) * mask;
    }
}

// ---------------- attention: 8 queries/block ----------------
#define QT 8
__global__ void attn_kernel(const float* __restrict__ qkv, float* __restrict__ ctx) {
    const int q0 = blockIdx.x * QT, hd = blockIdx.y, bb = blockIdx.z, tid = threadIdx.x;
    const int nkb = q0 + QT;
    __shared__ float sq[QT][DH]; __shared__ float sc[QT][SLEN];
    __shared__ float red[128]; __shared__ float sinv[QT];
    const size_t rb = (size_t)(bb * SLEN) * K3D + (size_t)hd * DH;

    for (int i = tid; i < QT * DH; i += 128)
        sq[i / DH][i % DH] = qkv[rb + (size_t)(q0 + i / DH) * K3D + (i % DH)] * 0.125f;
    __syncthreads();

    const float* kb = qkv + rb + D;
    for (int key = tid; key < nkb; key += 128) {
        const float* kr = kb + (size_t)key * K3D;
        float a[QT];
        #pragma unroll
        for (int qi = 0; qi < QT; qi++) a[qi] = 0.f;
        #pragma unroll 8
        for (int d = 0; d < DH; d++) {
            float kd = kr[d];
            #pragma unroll
            for (int qi = 0; qi < QT; qi++) a[qi] = fmaf(sq[qi][d], kd, a[qi]);
        }
        #pragma unroll
        for (int qi = 0; qi < QT; qi++) sc[qi][key] = a[qi];
    }
    __syncthreads();

    for (int qi = 0; qi < QT; qi++) {
        int bound = q0 + qi;
        float mx = -1e30f;
        for (int key = tid; key <= bound; key += 128) mx = fmaxf(mx, sc[qi][key]);
        red[tid] = mx; __syncthreads();
        #pragma unroll
        for (int o = 64; o; o >>= 1) { if (tid < o) red[tid] = fmaxf(red[tid], red[tid + o]); __syncthreads(); }
        mx = red[0]; __syncthreads();
        float s = 0.f;
        for (int key = tid; key < nkb; key += 128) {
            float e = (key <= bound) ? expf(sc[qi][key] - mx) : 0.f;
            sc[qi][key] = e; s += e;
        }
        red[tid] = s; __syncthreads();
        #pragma unroll
        for (int o = 64; o; o >>= 1) { if (tid < o) red[tid] += red[tid + o]; __syncthreads(); }
        if (tid == 0) sinv[qi] = 1.0f / red[0];
        __syncthreads();
    }

    const int d = tid & 63, half = tid >> 6;
    const float* vb = qkv + rb + 2 * D + d;
    float a[QT];
    #pragma unroll
    for (int qi = 0; qi < QT; qi++) a[qi] = 0.f;
    for (int key = half; key < nkb; key += 2) {
        float vv = vb[(size_t)key * K3D];
        #pragma unroll
        for (int qi = 0; qi < QT; qi++) a[qi] = fmaf(sc[qi][key], vv, a[qi]);
    }
    for (int qi = 0; qi < QT; qi++) {
        red[tid] = a[qi]; __syncthreads();
        if (tid < 64)
            ctx[((size_t)(bb * SLEN + q0 + qi)) * D + hd * DH + d] = (red[tid] + red[tid + 64]) * sinv[qi];
        __syncthreads();
    }
}

// ---------------- launcher ----------------
extern "C" void kernel_launch(void* const* d_in, const int* in_sizes, int n_in,
                              void* d_out, int out_size) {
    const int*   x   = (const int*)  d_in[0];
    const int*   len = (const int*)  d_in[1];
    const float* tok = (const float*)d_in[2];
    const float* pos = (const float*)d_in[3];
    const float* leg = (const float*)d_in[4];
    const float* leb = (const float*)d_in[5];
    const float* Wq = (const float*)d_in[6];  const float* bq = (const float*)d_in[7];
    const float* Wk = (const float*)d_in[8];  const float* bk = (const float*)d_in[9];
    const float* Wv = (const float*)d_in[10]; const float* bv = (const float*)d_in[11];
    const float* Wo = (const float*)d_in[12]; const float* bo = (const float*)d_in[13];
    const float* l1g = (const float*)d_in[14]; const float* l1b = (const float*)d_in[15];
    const float* W1 = (const float*)d_in[16]; const float* b1 = (const float*)d_in[17];
    const float* W2 = (const float*)d_in[18]; const float* b2 = (const float*)d_in[19];
    const float* l2g = (const float*)d_in[20]; const float* l2b = (const float*)d_in[21];
    const float* pW = (const float*)d_in[22]; const float* pb = (const float*)d_in[23];
    float* out = (float*)d_out;

    float *h, *qkv, *ctx, *tmp, *ff, *bqkv;
    __nv_bfloat16 *a3, *wqkv, *wo, *w1, *w2, *wp;
    cudaGetSymbolAddress((void**)&h, g_h);     cudaGetSymbolAddress((void**)&qkv, g_qkv);
    cudaGetSymbolAddress((void**)&ctx, g_ctx); cudaGetSymbolAddress((void**)&tmp, g_tmp);
    cudaGetSymbolAddress((void**)&ff, g_ff);   cudaGetSymbolAddress((void**)&bqkv, g_bqkv);
    cudaGetSymbolAddress((void**)&a3, g_a3);   cudaGetSymbolAddress((void**)&wqkv, g_wqkv);
    cudaGetSymbolAddress((void**)&wo, g_wo);   cudaGetSymbolAddress((void**)&w1, g_w1);
    cudaGetSymbolAddress((void**)&w2, g_w2);   cudaGetSymbolAddress((void**)&wp, g_wp);

    const int smemsz = NSTG * STGSZ;   // 3 * 36864 = 110592
    cudaFuncSetAttribute(gemm_kernel, cudaFuncAttributeMaxDynamicSharedMemorySize, smemsz);

    for (int i = 0; i < LYRS; i++) {
        size_t w = (size_t)i * D * D;
        convert_w<<<dim3(D/32, D/32), 256>>>(Wq + w, wqkv + (size_t)i*K3D*K3D, D, D, 0,   K3D);
        convert_w<<<dim3(D/32, D/32), 256>>>(Wk + w, wqkv + (size_t)i*K3D*K3D, D, D, D,   K3D);
        convert_w<<<dim3(D/32, D/32), 256>>>(Wv + w, wqkv + (size_t)i*K3D*K3D, D, D, 2*D, K3D);
        convert_w<<<dim3(D/32, D/32), 256>>>(Wo + w, wo + (size_t)i*D*K3D, D, D, 0, K3D);
        convert_w<<<dim3(D/32, FF/32), 256>>>(W1 + (size_t)i*D*FF, w1 + (size_t)i*FF*K3D, D, FF, 0, K3D);
        convert_w<<<dim3(FF/32, D/32), 256>>>(W2 + (size_t)i*FF*D, w2 + (size_t)i*D*K3F, FF, D, 0, K3F);
        concat_bias<<<4, 256>>>(bq + (size_t)i*D, bk + (size_t)i*D, bv + (size_t)i*D, bqkv + (size_t)i*K3D);
    }
    convert_w<<<dim3(D/32, V/32), 256>>>(pW, wp, D, V, 0, K3D);

    embed_ln_kernel<<<TOK, 256>>>(x, len, tok, pos, leg, leb, h);

    for (int i = 0; i < LYRS; i++) {
        convert_act<<<(TOK*(D/2)+255)/256, 256>>>(h, a3, D);
        gemm_kernel<<<dim3(TOK/128, K3D/128), 256, smemsz>>>(
            a3, wqkv + (size_t)i*K3D*K3D, bqkv + (size_t)i*K3D, qkv, K3D, K3D, 0);

        attn_kernel<<<dim3(SLEN/QT, H, BS), 128>>>(qkv, ctx);

        convert_act<<<(TOK*(D/2)+255)/256, 256>>>(ctx, a3, D);
        gemm_kernel<<<dim3(TOK/128, D/128), 256, smemsz>>>(
            a3, wo + (size_t)i*D*K3D, bo + (size_t)i*D, tmp, K3D, D, 0);
        add_ln_kernel<<<TOK, 256>>>(h, tmp, l1g + (size_t)i*D, l1b + (size_t)i*D, nullptr, h);

        convert_act<<<(TOK*(D/2)+255)/256, 256>>>(h, a3, D);
        gemm_kernel<<<dim3(TOK/128, FF/128), 256, smemsz>>>(
            a3, w1 + (size_t)i*FF*K3D, b1 + (size_t)i*FF, ff, K3D, FF, 1);

        convert_act<<<(TOK*(FF/2)+255)/256, 256>>>(ff, a3, FF);
        gemm_kernel<<<dim3(TOK/128, D/128), 256, smemsz>>>(
            a3, w2 + (size_t)i*D*K3F, b2 + (size_t)i*D, tmp, K3F, D, 0);
        add_ln_kernel<<<TOK, 256>>>(h, tmp, l2g + (size_t)i*D, l2b + (size_t)i*D, len, h);
    }

    convert_act<<<(TOK*(D/2)+255)/256, 256>>>(h, a3, D);
    gemm_kernel<<<dim3(TOK/128, V/128), 256, smemsz>>>(a3, wp, pb, out, K3D, V, 0);
}

// round 5
// speedup vs baseline: 3.7401x; 1.1809x over previous
#include <cuda_runtime.h>
#include <cuda_bf16.h>
#include <math.h>
#include <stdint.h>

#define LYRS 2
#define H 16
#define D 1024
#define DH 64
#define FF 4096
#define V 32000
#define SLEN 1024
#define BS 2
#define TOK (BS*SLEN)
#define EPS 1e-12f
#define K3D (3*D)

#define NSTG 3

// ---------------- scratch ----------------
__device__ float g_h  [TOK*D];
__device__ float g_qkv[TOK*K3D];
__device__ float g_tmp[TOK*D];
__device__ float g_bqkv[LYRS*K3D];
__device__ __align__(256) __nv_bfloat16 g_a3 [TOK*2*D];        // [hi|lo] activations, K=1024
__device__ __align__(256) __nv_bfloat16 g_s2 [TOK*2*FF];       // [hi|lo] ffn acts, K=4096
__device__ __align__(256) __nv_bfloat16 g_wqkv[LYRS*(size_t)K3D*2*D];
__device__ __align__(256) __nv_bfloat16 g_wo  [LYRS*(size_t)D*2*D];
__device__ __align__(256) __nv_bfloat16 g_w1  [LYRS*(size_t)FF*2*D];
__device__ __align__(256) __nv_bfloat16 g_w2  [LYRS*(size_t)D*2*FF];
__device__ __align__(256) __nv_bfloat16 g_wp  [(size_t)V*2*D];

// ---------------- helpers ----------------
__device__ __forceinline__ uint32_t s2u(const void* p) {
    uint32_t a;
    asm("{ .reg .u64 t; cvta.to.shared.u64 t, %1; cvt.u32.u64 %0, t; }" : "=r"(a) : "l"(p));
    return a;
}
__device__ __forceinline__ void cpa16(uint32_t dst, const void* src) {
    asm volatile("cp.async.cg.shared.global [%0], [%1], 16;" :: "r"(dst), "l"(src));
}
__device__ __forceinline__ void ldm4(uint32_t (&r)[4], uint32_t addr) {
    asm volatile("ldmatrix.sync.aligned.m8n8.x4.shared.b16 {%0,%1,%2,%3}, [%4];"
                 : "=r"(r[0]), "=r"(r[1]), "=r"(r[2]), "=r"(r[3]) : "r"(addr));
}
__device__ __forceinline__ void mma16816(float (&c)[4], const uint32_t a0, const uint32_t a1,
                                         const uint32_t a2, const uint32_t a3,
                                         const uint32_t b0, const uint32_t b1) {
    asm volatile("mma.sync.aligned.m16n8k16.row.col.f32.bf16.bf16.f32 "
                 "{%0,%1,%2,%3}, {%4,%5,%6,%7}, {%8,%9}, {%0,%1,%2,%3};"
                 : "+f"(c[0]), "+f"(c[1]), "+f"(c[2]), "+f"(c[3])
                 : "r"(a0), "r"(a1), "r"(a2), "r"(a3), "r"(b0), "r"(b1));
}
__device__ __forceinline__ void split2(float v, __nv_bfloat16& hi, __nv_bfloat16& lo) {
    hi = __float2bfloat16(v);
    lo = __float2bfloat16(v - __bfloat162float(hi));
}

// ---------------- weight conversion: W[K,N] f32 -> rows(rowOff+n)=[hi|lo], stride ld2 ----
__global__ void convert_w(const float* __restrict__ W, __nv_bfloat16* __restrict__ out,
                          int K, int N, int rowOff, int ld2) {
    __shared__ float t[32][33];
    int k0 = blockIdx.x * 32, n0 = blockIdx.y * 32;
    int tx = threadIdx.x & 31, ty = threadIdx.x >> 5;
    #pragma unroll
    for (int i = 0; i < 4; i++)
        t[ty + i * 8][tx] = W[(size_t)(k0 + ty + i * 8) * N + n0 + tx];
    __syncthreads();
    #pragma unroll
    for (int i = 0; i < 4; i++) {
        int n = n0 + ty + i * 8, k = k0 + tx;
        __nv_bfloat16 hi, lo;
        split2(t[tx][ty + i * 8], hi, lo);
        __nv_bfloat16* o = out + (size_t)(rowOff + n) * ld2;
        o[k] = hi; o[K + k] = lo;
    }
}
__global__ void concat_bias(const float* __restrict__ a, const float* __restrict__ b,
                            const float* __restrict__ c, float* __restrict__ o) {
    int i = blockIdx.x * 256 + threadIdx.x;
    if (i < D) { o[i] = a[i]; o[D + i] = b[i]; o[2 * D + i] = c[i]; }
}

// ---------------- GEMM: C[2048,N] = A @ B^T (+bias,+gelu), bf16x3 via 3-phase [hi|lo] ----
// Tile 128 x (WN*64), threads 128*WN, warps 4 x WN, warp tile 32x64.
template<int WN>
__global__ void __launch_bounds__(128*WN, 1) gemm_kernel(
    const __nv_bfloat16* __restrict__ A, const __nv_bfloat16* __restrict__ B,
    const float* __restrict__ bias, float* __restrict__ C, __nv_bfloat16* __restrict__ S,
    int Kp, int N, int act)
{
    constexpr int BN = WN * 64;
    constexpr int THR = 128 * WN;
    constexpr int TBA = 128 * 144;
    constexpr int TBB = BN * 144;
    constexpr int STG = TBA + TBB;
    extern __shared__ __align__(128) char smem[];
    const int tid = threadIdx.x, wid = tid >> 5, lane = tid & 31;
    const int wm = wid & 3, wn = wid >> 2;
    const int m0 = blockIdx.x * 128, n0 = blockIdx.y * BN;
    const uint32_t sb = s2u(smem);
    const size_t rs = 2 * (size_t)Kp;

    float acc[2][8][4];
    #pragma unroll
    for (int mi = 0; mi < 2; mi++)
        #pragma unroll
        for (int ni = 0; ni < 8; ni++)
            #pragma unroll
            for (int j = 0; j < 4; j++) acc[mi][ni][j] = 0.f;

    const int nch0 = Kp / 64, nch = 3 * nch0;

    auto load_chunk = [&](int c) {
        int p = c / nch0, kk = c - p * nch0;
        int aoff = ((p == 2) ? Kp : 0) + kk * 64;
        int boff = ((p == 1) ? Kp : 0) + kk * 64;
        uint32_t base = sb + (c % NSTG) * STG;
        const __nv_bfloat16* Ag = A + (size_t)m0 * rs + aoff;
        const __nv_bfloat16* Bg = B + (size_t)n0 * rs + boff;
        #pragma unroll
        for (int j = 0; j < 8 / WN; j++) {
            int idx = tid + j * THR;
            int r = idx >> 3, ch = idx & 7;
            cpa16(base + r * 144 + ch * 16, (const char*)(Ag + (size_t)r * rs) + ch * 16);
        }
        #pragma unroll
        for (int j = 0; j < 4; j++) {
            int idx = tid + j * THR;
            int r = idx >> 3, ch = idx & 7;
            cpa16(base + TBA + r * 144 + ch * 16, (const char*)(Bg + (size_t)r * rs) + ch * 16);
        }
    };

    load_chunk(0);
    asm volatile("cp.async.commit_group;" ::: "memory");
    load_chunk(1);
    asm volatile("cp.async.commit_group;" ::: "memory");

    const int lq = lane & 7, lh = (lane >> 3) & 1, lk = lane >> 4;
    const uint32_t aOff = (uint32_t)((wm * 32 + lh * 8 + lq) * 144 + lk * 16);
    const uint32_t bOff = (uint32_t)(TBA + (wn * 64 + lh * 8 + lq) * 144 + lk * 16);

    for (int c = 0; c < nch; c++) {
        asm volatile("cp.async.wait_group 1;" ::: "memory");
        __syncthreads();
        if (c + 2 < nch) load_chunk(c + 2);
        asm volatile("cp.async.commit_group;" ::: "memory");

        uint32_t stg = sb + (c % NSTG) * STG;
        #pragma unroll
        for (int ks = 0; ks < 4; ks++) {
            uint32_t a0[4], a1[4], bf[4][4];
            ldm4(a0, stg + aOff + ks * 32);
            ldm4(a1, stg + aOff + 16 * 144 + ks * 32);
            #pragma unroll
            for (int nt = 0; nt < 4; nt++)
                ldm4(bf[nt], stg + bOff + nt * 16 * 144 + ks * 32);
            #pragma unroll
            for (int ni = 0; ni < 8; ni++) {
                uint32_t b0 = bf[ni >> 1][ni & 1], b1 = bf[ni >> 1][(ni & 1) + 2];
                mma16816(acc[0][ni], a0[0], a0[1], a0[2], a0[3], b0, b1);
                mma16816(acc[1][ni], a1[0], a1[1], a1[2], a1[3], b0, b1);
            }
        }
        __syncthreads();
    }

    const int r0 = lane >> 2, cp = (lane & 3) * 2;
    #pragma unroll
    for (int mi = 0; mi < 2; mi++) {
        #pragma unroll
        for (int ni = 0; ni < 8; ni++) {
            int col = n0 + wn * 64 + ni * 8 + cp;
            float bb0 = bias[col], bb1 = bias[col + 1];
            #pragma unroll
            for (int half = 0; half < 2; half++) {
                int row = m0 + wm * 32 + mi * 16 + r0 + half * 8;
                float v0 = acc[mi][ni][half * 2 + 0] + bb0;
                float v1 = acc[mi][ni][half * 2 + 1] + bb1;
                if (act) {
                    v0 = 0.5f * v0 * (1.0f + erff(v0 * 0.70710678118654752f));
                    v1 = 0.5f * v1 * (1.0f + erff(v1 * 0.70710678118654752f));
                }
                if (C) {
                    float2 o; o.x = v0; o.y = v1;
                    *(float2*)(C + (size_t)row * N + col) = o;
                }
                if (S) {
                    __nv_bfloat162 h2, l2;
                    split2(v0, h2.x, l2.x); split2(v1, h2.y, l2.y);
                    *(__nv_bfloat162*)(S + (size_t)row * 2 * N + col) = h2;
                    *(__nv_bfloat162*)(S + (size_t)row * 2 * N + N + col) = l2;
                }
            }
        }
    }
}

// ---------------- LayerNorm (writes f32 + [hi|lo] split) ----------------
__device__ __forceinline__ float brsum(float v, float* sbuf) {
    int tid = threadIdx.x;
    #pragma unroll
    for (int o = 16; o; o >>= 1) v += __shfl_down_sync(0xffffffffu, v, o);
    if ((tid & 31) == 0) sbuf[tid >> 5] = v;
    __syncthreads();
    if (tid < 8) {
        v = sbuf[tid];
        #pragma unroll
        for (int o = 4; o; o >>= 1) v += __shfl_down_sync(0xffu, v, o);
        if (tid == 0) sbuf[0] = v;
    }
    __syncthreads();
    float r = sbuf[0];
    __syncthreads();
    return r;
}
__global__ void embed_ln_kernel(const int* __restrict__ x, const int* __restrict__ len,
                                const float* __restrict__ tok, const float* __restrict__ pos,
                                const float* __restrict__ g, const float* __restrict__ b,
                                float* __restrict__ out, __nv_bfloat16* __restrict__ sp) {
    int row = blockIdx.x, bi = row / SLEN, s = row % SLEN, token = x[row], tid = threadIdx.x;
    __shared__ float buf[D]; __shared__ float red[8];
    float ls = 0.f;
    #pragma unroll
    for (int i = 0; i < 4; i++) {
        int c = tid + i * 256;
        float v = tok[(size_t)token * D + c] + pos[(size_t)s * D + c];
        buf[c] = v; ls += v;
    }
    float mean = brsum(ls, red) * (1.0f / D), ss = 0.f;
    #pragma unroll
    for (int i = 0; i < 4; i++) { float d = buf[tid + i * 256] - mean; ss += d * d; }
    float rstd = rsqrtf(brsum(ss, red) * (1.0f / D) + EPS);
    float mask = (s < len[bi]) ? 1.0f : 0.0f;
    #pragma unroll
    for (int i = 0; i < 4; i++) {
        int c = tid + i * 256;
        float v = (g[c] * (buf[c] - mean) * rstd + b[c]) * mask;
        out[(size_t)row * D + c] = v;
        __nv_bfloat16 hi, lo; split2(v, hi, lo);
        sp[(size_t)row * 2 * D + c] = hi;
        sp[(size_t)row * 2 * D + D + c] = lo;
    }
}
__global__ void add_ln_kernel(const float* __restrict__ a, const float* __restrict__ dl,
                              const float* __restrict__ g, const float* __restrict__ b,
                              const int* __restrict__ len, float* __restrict__ out,
                              __nv_bfloat16* __restrict__ sp) {
    int row = blockIdx.x, bi = row / SLEN, s = row % SLEN, tid = threadIdx.x;
    __shared__ float buf[D]; __shared__ float red[8];
    float ls = 0.f;
    #pragma unroll
    for (int i = 0; i < 4; i++) {
        int c = tid + i * 256;
        float v = a[(size_t)row * D + c] + dl[(size_t)row * D + c];
        buf[c] = v; ls += v;
    }
    float mean = brsum(ls, red) * (1.0f / D), ss = 0.f;
    #pragma unroll
    for (int i = 0; i < 4; i++) { float d = buf[tid + i * 256] - mean; ss += d * d; }
    float rstd = rsqrtf(brsum(ss, red) * (1.0f / D) + EPS);
    float mask = len ? ((s < len[bi]) ? 1.0f : 0.0f) : 1.0f;
    #pragma unroll
    for (int i = 0; i < 4; i++) {
        int c = tid + i * 256;
        float v = (g[c] * (buf[c] - mean) * rstd + b[c]) * mask;
        out[(size_t)row * D + c] = v;
        __nv_bfloat16 hi, lo; split2(v, hi, lo);
        sp[(size_t)row * 2 * D + c] = hi;
        sp[(size_t)row * 2 * D + D + c] = lo;
    }
}

// ---------------- attention: 8 queries/block, smem-staged K ----------------
#define QT 8
#define KCH 128
#define ATTN_SMEM ((QT*DH + QT*SLEN + KCH*65 + 128 + QT) * 4)
__global__ void attn_kernel(const float* __restrict__ qkv, __nv_bfloat16* __restrict__ a3) {
    extern __shared__ float sm[];
    float* sq = sm;                       // QT*64
    float* sc = sq + QT * DH;             // QT*1024
    float* sk = sc + QT * SLEN;           // KCH*65
    float* red = sk + KCH * 65;           // 128
    float* sinv = red + 128;              // QT
    const int q0 = blockIdx.x * QT, hd = blockIdx.y, bb = blockIdx.z, tid = threadIdx.x;
    const int nkb = q0 + QT;
    const size_t rb = (size_t)(bb * SLEN) * K3D + (size_t)hd * DH;

    for (int i = tid; i < QT * DH; i += 128)
        sq[i] = qkv[rb + (size_t)(q0 + i / DH) * K3D + (i % DH)] * 0.125f;
    __syncthreads();

    const float* kb = qkv + rb + D;
    for (int c0 = 0; c0 < nkb; c0 += KCH) {
        int rows = nkb - c0; if (rows > KCH) rows = KCH;
        for (int idx = tid; idx < rows * 16; idx += 128) {
            int r = idx >> 4, c4 = (idx & 15) * 4;
            float4 v = *(const float4*)(kb + (size_t)(c0 + r) * K3D + c4);
            sk[r * 65 + c4 + 0] = v.x; sk[r * 65 + c4 + 1] = v.y;
            sk[r * 65 + c4 + 2] = v.z; sk[r * 65 + c4 + 3] = v.w;
        }
        __syncthreads();
        for (int key = tid; key < rows; key += 128) {
            float a[QT];
            #pragma unroll
            for (int qi = 0; qi < QT; qi++) a[qi] = 0.f;
            #pragma unroll 8
            for (int d = 0; d < DH; d++) {
                float kd = sk[key * 65 + d];
                #pragma unroll
                for (int qi = 0; qi < QT; qi++) a[qi] = fmaf(sq[qi * DH + d], kd, a[qi]);
            }
            #pragma unroll
            for (int qi = 0; qi < QT; qi++) sc[qi * SLEN + c0 + key] = a[qi];
        }
        __syncthreads();
    }

    for (int qi = 0; qi < QT; qi++) {
        int bound = q0 + qi;
        float mx = -1e30f;
        for (int key = tid; key <= bound; key += 128) mx = fmaxf(mx, sc[qi * SLEN + key]);
        red[tid] = mx; __syncthreads();
        #pragma unroll
        for (int o = 64; o; o >>= 1) { if (tid < o) red[tid] = fmaxf(red[tid], red[tid + o]); __syncthreads(); }
        mx = red[0]; __syncthreads();
        float s = 0.f;
        for (int key = tid; key < nkb; key += 128) {
            float e = (key <= bound) ? expf(sc[qi * SLEN + key] - mx) : 0.f;
            sc[qi * SLEN + key] = e; s += e;
        }
        red[tid] = s; __syncthreads();
        #pragma unroll
        for (int o = 64; o; o >>= 1) { if (tid < o) red[tid] += red[tid + o]; __syncthreads(); }
        if (tid == 0) sinv[qi] = 1.0f / red[0];
        __syncthreads();
    }

    const int d = tid & 63, half = tid >> 6;
    const float* vb = qkv + rb + 2 * D + d;
    float a[QT];
    #pragma unroll
    for (int qi = 0; qi < QT; qi++) a[qi] = 0.f;
    for (int key = half; key < nkb; key += 2) {
        float vv = vb[(size_t)key * K3D];
        #pragma unroll
        for (int qi = 0; qi < QT; qi++) a[qi] = fmaf(sc[qi * SLEN + key], vv, a[qi]);
    }
    for (int qi = 0; qi < QT; qi++) {
        red[tid] = a[qi]; __syncthreads();
        if (tid < 64) {
            float v = (red[tid] + red[tid + 64]) * sinv[qi];
            size_t row = (size_t)(bb * SLEN + q0 + qi);
            __nv_bfloat16 hi, lo; split2(v, hi, lo);
            a3[row * 2 * D + hd * DH + d] = hi;
            a3[row * 2 * D + D + hd * DH + d] = lo;
        }
        __syncthreads();
    }
}

// ---------------- launcher ----------------
extern "C" void kernel_launch(void* const* d_in, const int* in_sizes, int n_in,
                              void* d_out, int out_size) {
    const int*   x   = (const int*)  d_in[0];
    const int*   len = (const int*)  d_in[1];
    const float* tok = (const float*)d_in[2];
    const float* pos = (const float*)d_in[3];
    const float* leg = (const float*)d_in[4];
    const float* leb = (const float*)d_in[5];
    const float* Wq = (const float*)d_in[6];  const float* bq = (const float*)d_in[7];
    const float* Wk = (const float*)d_in[8];  const float* bk = (const float*)d_in[9];
    const float* Wv = (const float*)d_in[10]; const float* bv = (const float*)d_in[11];
    const float* Wo = (const float*)d_in[12]; const float* bo = (const float*)d_in[13];
    const float* l1g = (const float*)d_in[14]; const float* l1b = (const float*)d_in[15];
    const float* W1 = (const float*)d_in[16]; const float* b1 = (const float*)d_in[17];
    const float* W2 = (const float*)d_in[18]; const float* b2 = (const float*)d_in[19];
    const float* l2g = (const float*)d_in[20]; const float* l2b = (const float*)d_in[21];
    const float* pW = (const float*)d_in[22]; const float* pb = (const float*)d_in[23];
    float* out = (float*)d_out;

    float *h, *qkv, *tmp, *bqkv;
    __nv_bfloat16 *a3, *s2, *wqkv, *wo, *w1, *w2, *wp;
    cudaGetSymbolAddress((void**)&h, g_h);     cudaGetSymbolAddress((void**)&qkv, g_qkv);
    cudaGetSymbolAddress((void**)&tmp, g_tmp); cudaGetSymbolAddress((void**)&bqkv, g_bqkv);
    cudaGetSymbolAddress((void**)&a3, g_a3);   cudaGetSymbolAddress((void**)&s2, g_s2);
    cudaGetSymbolAddress((void**)&wqkv, g_wqkv); cudaGetSymbolAddress((void**)&wo, g_wo);
    cudaGetSymbolAddress((void**)&w1, g_w1);   cudaGetSymbolAddress((void**)&w2, g_w2);
    cudaGetSymbolAddress((void**)&wp, g_wp);

    const int sm2 = NSTG * (128 + 128) * 144;   // 110592
    const int sm4 = NSTG * (128 + 256) * 144;   // 165888
    cudaFuncSetAttribute(gemm_kernel<2>, cudaFuncAttributeMaxDynamicSharedMemorySize, sm2);
    cudaFuncSetAttribute(gemm_kernel<4>, cudaFuncAttributeMaxDynamicSharedMemorySize, sm4);
    cudaFuncSetAttribute(attn_kernel, cudaFuncAttributeMaxDynamicSharedMemorySize, ATTN_SMEM);

    for (int i = 0; i < LYRS; i++) {
        size_t w = (size_t)i * D * D;
        __nv_bfloat16* wq3 = wqkv + (size_t)i * K3D * 2 * D;
        convert_w<<<dim3(D/32, D/32), 256>>>(Wq + w, wq3, D, D, 0,   2*D);
        convert_w<<<dim3(D/32, D/32), 256>>>(Wk + w, wq3, D, D, D,   2*D);
        convert_w<<<dim3(D/32, D/32), 256>>>(Wv + w, wq3, D, D, 2*D, 2*D);
        convert_w<<<dim3(D/32, D/32), 256>>>(Wo + w, wo + (size_t)i*D*2*D, D, D, 0, 2*D);
        convert_w<<<dim3(D/32, FF/32), 256>>>(W1 + (size_t)i*D*FF, w1 + (size_t)i*FF*2*D, D, FF, 0, 2*D);
        convert_w<<<dim3(FF/32, D/32), 256>>>(W2 + (size_t)i*FF*D, w2 + (size_t)i*D*2*FF, FF, D, 0, 2*FF);
        concat_bias<<<4, 256>>>(bq + (size_t)i*D, bk + (size_t)i*D, bv + (size_t)i*D, bqkv + (size_t)i*K3D);
    }
    convert_w<<<dim3(D/32, V/32), 256>>>(pW, wp, D, V, 0, 2*D);

    embed_ln_kernel<<<TOK, 256>>>(x, len, tok, pos, leg, leb, h, a3);

    for (int i = 0; i < LYRS; i++) {
        gemm_kernel<4><<<dim3(TOK/128, K3D/256), 512, sm4>>>(
            a3, wqkv + (size_t)i*K3D*2*D, bqkv + (size_t)i*K3D, qkv, (__nv_bfloat16*)0, D, K3D, 0);

        attn_kernel<<<dim3(SLEN/QT, H, BS), 128, ATTN_SMEM>>>(qkv, a3);

        gemm_kernel<2><<<dim3(TOK/128, D/128), 256, sm2>>>(
            a3, wo + (size_t)i*D*2*D, bo + (size_t)i*D, tmp, (__nv_bfloat16*)0, D, D, 0);
        add_ln_kernel<<<TOK, 256>>>(h, tmp, l1g + (size_t)i*D, l1b + (size_t)i*D, (const int*)0, h, a3);

        gemm_kernel<4><<<dim3(TOK/128, FF/256), 512, sm4>>>(
            a3, w1 + (size_t)i*FF*2*D, b1 + (size_t)i*FF, (float*)0, s2, D, FF, 1);

        gemm_kernel<2><<<dim3(TOK/128, D/128), 256, sm2>>>(
            s2, w2 + (size_t)i*D*2*FF, b2 + (size_t)i*D, tmp, (__nv_bfloat16*)0, FF, D, 0);
        add_ln_kernel<<<TOK, 256>>>(h, tmp, l2g + (size_t)i*D, l2b + (size_t)i*D, len, h, a3);
    }

    gemm_kernel<4><<<dim3(TOK/128, V/256), 512, sm4>>>(
        a3, wp, pb, out, (__nv_bfloat16*)0, D, V, 0);
}

// round 6
// speedup vs baseline: 3.7402x; 1.0000x over previous
#include <cuda_runtime.h>
#include <cuda_bf16.h>
#include <math.h>
#include <stdint.h>

#define LYRS 2
#define H 16
#define D 1024
#define DH 64
#define FF 4096
#define V 32000
#define SLEN 1024
#define BS 2
#define TOK (BS*SLEN)
#define EPS 1e-12f
#define K3D (3*D)
#define NSTG 3

// ---------------- scratch ----------------
__device__ float g_h  [TOK*D];
__device__ float g_qkv[TOK*K3D];
__device__ float g_tmp[TOK*D];
__device__ float g_bqkv[LYRS*K3D];
__device__ __align__(256) __nv_bfloat16 g_a3 [TOK*2*D];
__device__ __align__(256) __nv_bfloat16 g_s2 [TOK*2*FF];
__device__ __align__(256) __nv_bfloat16 g_wqkv[LYRS*(size_t)K3D*2*D];
__device__ __align__(256) __nv_bfloat16 g_wo  [LYRS*(size_t)D*2*D];
__device__ __align__(256) __nv_bfloat16 g_w1  [LYRS*(size_t)FF*2*D];
__device__ __align__(256) __nv_bfloat16 g_w2  [LYRS*(size_t)D*2*FF];
__device__ __align__(256) __nv_bfloat16 g_wp  [(size_t)V*2*D];

// ---------------- helpers ----------------
__device__ __forceinline__ uint32_t s2u(const void* p) {
    uint32_t a;
    asm("{ .reg .u64 t; cvta.to.shared.u64 t, %1; cvt.u32.u64 %0, t; }" : "=r"(a) : "l"(p));
    return a;
}
__device__ __forceinline__ void cpa16(uint32_t dst, const void* src) {
    asm volatile("cp.async.cg.shared.global [%0], [%1], 16;" :: "r"(dst), "l"(src));
}
__device__ __forceinline__ void ldm4(uint32_t (&r)[4], uint32_t addr) {
    asm volatile("ldmatrix.sync.aligned.m8n8.x4.shared.b16 {%0,%1,%2,%3}, [%4];"
                 : "=r"(r[0]), "=r"(r[1]), "=r"(r[2]), "=r"(r[3]) : "r"(addr));
}
__device__ __forceinline__ void mma16816(float (&c)[4], const uint32_t a0, const uint32_t a1,
                                         const uint32_t a2, const uint32_t a3,
                                         const uint32_t b0, const uint32_t b1) {
    asm volatile("mma.sync.aligned.m16n8k16.row.col.f32.bf16.bf16.f32 "
                 "{%0,%1,%2,%3}, {%4,%5,%6,%7}, {%8,%9}, {%0,%1,%2,%3};"
                 : "+f"(c[0]), "+f"(c[1]), "+f"(c[2]), "+f"(c[3])
                 : "r"(a0), "r"(a1), "r"(a2), "r"(a3), "r"(b0), "r"(b1));
}
__device__ __forceinline__ void split2(float v, __nv_bfloat16& hi, __nv_bfloat16& lo) {
    hi = __float2bfloat16(v);
    lo = __float2bfloat16(v - __bfloat162float(hi));
}

// ---------------- weight conversion ----------------
__global__ void convert_w(const float* __restrict__ W, __nv_bfloat16* __restrict__ out,
                          int K, int N, int rowOff, int ld2) {
    __shared__ float t[32][33];
    int k0 = blockIdx.x * 32, n0 = blockIdx.y * 32;
    int tx = threadIdx.x & 31, ty = threadIdx.x >> 5;
    #pragma unroll
    for (int i = 0; i < 4; i++)
        t[ty + i * 8][tx] = W[(size_t)(k0 + ty + i * 8) * N + n0 + tx];
    __syncthreads();
    #pragma unroll
    for (int i = 0; i < 4; i++) {
        int n = n0 + ty + i * 8, k = k0 + tx;
        __nv_bfloat16 hi, lo;
        split2(t[tx][ty + i * 8], hi, lo);
        __nv_bfloat16* o = out + (size_t)(rowOff + n) * ld2;
        o[k] = hi; o[K + k] = lo;
    }
}
__global__ void concat_bias(const float* __restrict__ a, const float* __restrict__ b,
                            const float* __restrict__ c, float* __restrict__ o) {
    int i = blockIdx.x * 256 + threadIdx.x;
    if (i < D) { o[i] = a[i]; o[D + i] = b[i]; o[2 * D + i] = c[i]; }
}

// ---------------- GEMM: C[2048,N] = A @ B^T, bf16x3 3-phase, warp tile 64x64 ----
// CTA tile 128 x (64*WNW); warps 2(M) x WNW(N); threads 64*WNW.
template<int WNW>
__global__ void __launch_bounds__(64*WNW, 1) gemm_kernel(
    const __nv_bfloat16* __restrict__ A, const __nv_bfloat16* __restrict__ B,
    const float* __restrict__ bias, float* __restrict__ C, __nv_bfloat16* __restrict__ S,
    int Kp, int N, int act)
{
    constexpr int BN = WNW * 64;
    constexpr int THR = 64 * WNW;
    constexpr int TBA = 128 * 144;
    constexpr int STG = TBA + BN * 144;
    extern __shared__ __align__(128) char smem[];
    const int tid = threadIdx.x, wid = tid >> 5, lane = tid & 31;
    const int wm = wid & 1, wn = wid >> 1;
    const int m0 = blockIdx.x * 128, n0 = blockIdx.y * BN;
    const uint32_t sb = s2u(smem);
    const size_t rs = 2 * (size_t)Kp;

    float acc[4][8][4];
    #pragma unroll
    for (int mi = 0; mi < 4; mi++)
        #pragma unroll
        for (int ni = 0; ni < 8; ni++)
            #pragma unroll
            for (int j = 0; j < 4; j++) acc[mi][ni][j] = 0.f;

    const int nch0 = Kp / 64, nch = 3 * nch0;

    auto load_chunk = [&](int c) {
        int p = c / nch0, kk = c - p * nch0;
        int aoff = ((p == 2) ? Kp : 0) + kk * 64;
        int boff = ((p == 1) ? Kp : 0) + kk * 64;
        uint32_t base = sb + (c % NSTG) * STG;
        const __nv_bfloat16* Ag = A + (size_t)m0 * rs + aoff;
        const __nv_bfloat16* Bg = B + (size_t)n0 * rs + boff;
        #pragma unroll
        for (int j = 0; j < 1024 / THR; j++) {
            int idx = tid + j * THR;
            int r = idx >> 3, ch = idx & 7;
            cpa16(base + r * 144 + ch * 16, (const char*)(Ag + (size_t)r * rs) + ch * 16);
        }
        #pragma unroll
        for (int j = 0; j < 8; j++) {
            int idx = tid + j * THR;
            int r = idx >> 3, ch = idx & 7;
            cpa16(base + TBA + r * 144 + ch * 16, (const char*)(Bg + (size_t)r * rs) + ch * 16);
        }
    };

    load_chunk(0);
    asm volatile("cp.async.commit_group;" ::: "memory");
    load_chunk(1);
    asm volatile("cp.async.commit_group;" ::: "memory");

    const int lq = lane & 7, lh = (lane >> 3) & 1, lk = lane >> 4;
    const uint32_t aOff = (uint32_t)((wm * 64 + lh * 8 + lq) * 144 + lk * 16);
    const uint32_t bOff = (uint32_t)(TBA + (wn * 64 + lh * 8 + lq) * 144 + lk * 16);

    for (int c = 0; c < nch; c++) {
        asm volatile("cp.async.wait_group 1;" ::: "memory");
        __syncthreads();
        if (c + 2 < nch) load_chunk(c + 2);
        asm volatile("cp.async.commit_group;" ::: "memory");

        uint32_t stg = sb + (c % NSTG) * STG;
        #pragma unroll
        for (int ks = 0; ks < 4; ks++) {
            uint32_t af[4][4], bf[4][4];
            #pragma unroll
            for (int mt = 0; mt < 4; mt++)
                ldm4(af[mt], stg + aOff + mt * 16 * 144 + ks * 32);
            #pragma unroll
            for (int nt = 0; nt < 4; nt++)
                ldm4(bf[nt], stg + bOff + nt * 16 * 144 + ks * 32);
            #pragma unroll
            for (int mi = 0; mi < 4; mi++)
                #pragma unroll
                for (int ni = 0; ni < 8; ni++) {
                    uint32_t b0 = bf[ni >> 1][ni & 1], b1 = bf[ni >> 1][(ni & 1) + 2];
                    mma16816(acc[mi][ni], af[mi][0], af[mi][1], af[mi][2], af[mi][3], b0, b1);
                }
        }
        __syncthreads();
    }

    const int r0 = lane >> 2, cp = (lane & 3) * 2;
    #pragma unroll
    for (int mi = 0; mi < 4; mi++) {
        #pragma unroll
        for (int ni = 0; ni < 8; ni++) {
            int col = n0 + wn * 64 + ni * 8 + cp;
            float bb0 = bias[col], bb1 = bias[col + 1];
            #pragma unroll
            for (int half = 0; half < 2; half++) {
                int row = m0 + wm * 64 + mi * 16 + r0 + half * 8;
                float v0 = acc[mi][ni][half * 2 + 0] + bb0;
                float v1 = acc[mi][ni][half * 2 + 1] + bb1;
                if (act) {
                    v0 = 0.5f * v0 * (1.0f + erff(v0 * 0.70710678118654752f));
                    v1 = 0.5f * v1 * (1.0f + erff(v1 * 0.70710678118654752f));
                }
                if (C) {
                    float2 o; o.x = v0; o.y = v1;
                    *(float2*)(C + (size_t)row * N + col) = o;
                }
                if (S) {
                    __nv_bfloat162 h2, l2;
                    split2(v0, h2.x, l2.x); split2(v1, h2.y, l2.y);
                    *(__nv_bfloat162*)(S + (size_t)row * 2 * N + col) = h2;
                    *(__nv_bfloat162*)(S + (size_t)row * 2 * N + N + col) = l2;
                }
            }
        }
    }
}

// ---------------- LayerNorm ----------------
__device__ __forceinline__ float brsum(float v, float* sbuf) {
    int tid = threadIdx.x;
    #pragma unroll
    for (int o = 16; o; o >>= 1) v += __shfl_down_sync(0xffffffffu, v, o);
    if ((tid & 31) == 0) sbuf[tid >> 5] = v;
    __syncthreads();
    if (tid < 8) {
        v = sbuf[tid];
        #pragma unroll
        for (int o = 4; o; o >>= 1) v += __shfl_down_sync(0xffu, v, o);
        if (tid == 0) sbuf[0] = v;
    }
    __syncthreads();
    float r = sbuf[0];
    __syncthreads();
    return r;
}
__global__ void embed_ln_kernel(const int* __restrict__ x, const int* __restrict__ len,
                                const float* __restrict__ tok, const float* __restrict__ pos,
                                const float* __restrict__ g, const float* __restrict__ b,
                                float* __restrict__ out, __nv_bfloat16* __restrict__ sp) {
    int row = blockIdx.x, bi = row / SLEN, s = row % SLEN, token = x[row], tid = threadIdx.x;
    __shared__ float buf[D]; __shared__ float red[8];
    float ls = 0.f;
    #pragma unroll
    for (int i = 0; i < 4; i++) {
        int c = tid + i * 256;
        float v = tok[(size_t)token * D + c] + pos[(size_t)s * D + c];
        buf[c] = v; ls += v;
    }
    float mean = brsum(ls, red) * (1.0f / D), ss = 0.f;
    #pragma unroll
    for (int i = 0; i < 4; i++) { float d = buf[tid + i * 256] - mean; ss += d * d; }
    float rstd = rsqrtf(brsum(ss, red) * (1.0f / D) + EPS);
    float mask = (s < len[bi]) ? 1.0f : 0.0f;
    #pragma unroll
    for (int i = 0; i < 4; i++) {
        int c = tid + i * 256;
        float v = (g[c] * (buf[c] - mean) * rstd + b[c]) * mask;
        out[(size_t)row * D + c] = v;
        __nv_bfloat16 hi, lo; split2(v, hi, lo);
        sp[(size_t)row * 2 * D + c] = hi;
        sp[(size_t)row * 2 * D + D + c] = lo;
    }
}
__global__ void add_ln_kernel(const float* __restrict__ a, const float* __restrict__ dl,
                              const float* __restrict__ g, const float* __restrict__ b,
                              const int* __restrict__ len, float* __restrict__ out,
                              __nv_bfloat16* __restrict__ sp) {
    int row = blockIdx.x, bi = row / SLEN, s = row % SLEN, tid = threadIdx.x;
    __shared__ float buf[D]; __shared__ float red[8];
    float ls = 0.f;
    #pragma unroll
    for (int i = 0; i < 4; i++) {
        int c = tid + i * 256;
        float v = a[(size_t)row * D + c] + dl[(size_t)row * D + c];
        buf[c] = v; ls += v;
    }
    float mean = brsum(ls, red) * (1.0f / D), ss = 0.f;
    #pragma unroll
    for (int i = 0; i < 4; i++) { float d = buf[tid + i * 256] - mean; ss += d * d; }
    float rstd = rsqrtf(brsum(ss, red) * (1.0f / D) + EPS);
    float mask = len ? ((s < len[bi]) ? 1.0f : 0.0f) : 1.0f;
    #pragma unroll
    for (int i = 0; i < 4; i++) {
        int c = tid + i * 256;
        float v = (g[c] * (buf[c] - mean) * rstd + b[c]) * mask;
        out[(size_t)row * D + c] = v;
        __nv_bfloat16 hi, lo; split2(v, hi, lo);
        sp[(size_t)row * 2 * D + c] = hi;
        sp[(size_t)row * 2 * D + D + c] = lo;
    }
}

// ---------------- attention: 8 q/block, smem-staged K and V, warp softmax ----
#define QT 8
#define KCH 128
#define ATTN_SMEM ((QT*DH + QT*SLEN + KCH*65 + QT) * 4)
__global__ void attn_kernel(const float* __restrict__ qkv, __nv_bfloat16* __restrict__ a3) {
    extern __shared__ float sm[];
    float* sq = sm;                       // QT*64
    float* sc = sq + QT * DH;             // QT*1024
    float* sk = sc + QT * SLEN;           // KCH*65 (K then V chunks)
    float* sinv = sk + KCH * 65;          // QT
    const int q0 = blockIdx.x * QT, hd = blockIdx.y, bb = blockIdx.z, tid = threadIdx.x;
    const int wid = tid >> 5, lane = tid & 31;
    const int nkb = q0 + QT;
    const size_t rb = (size_t)(bb * SLEN) * K3D + (size_t)hd * DH;

    for (int i = tid; i < QT * DH; i += 128)
        sq[i] = qkv[rb + (size_t)(q0 + i / DH) * K3D + (i % DH)] * 0.125f;
    __syncthreads();

    // scores
    const float* kb = qkv + rb + D;
    for (int c0 = 0; c0 < nkb; c0 += KCH) {
        int rows = nkb - c0; if (rows > KCH) rows = KCH;
        for (int idx = tid; idx < rows * 16; idx += 128) {
            int r = idx >> 4, c4 = (idx & 15) * 4;
            float4 v = *(const float4*)(kb + (size_t)(c0 + r) * K3D + c4);
            sk[r * 65 + c4 + 0] = v.x; sk[r * 65 + c4 + 1] = v.y;
            sk[r * 65 + c4 + 2] = v.z; sk[r * 65 + c4 + 3] = v.w;
        }
        __syncthreads();
        for (int key = tid; key < rows; key += 128) {
            float a[QT];
            #pragma unroll
            for (int qi = 0; qi < QT; qi++) a[qi] = 0.f;
            #pragma unroll 8
            for (int d = 0; d < DH; d++) {
                float kd = sk[key * 65 + d];
                #pragma unroll
                for (int qi = 0; qi < QT; qi++) a[qi] = fmaf(sq[qi * DH + d], kd, a[qi]);
            }
            #pragma unroll
            for (int qi = 0; qi < QT; qi++) sc[qi * SLEN + c0 + key] = a[qi];
        }
        __syncthreads();
    }

    // softmax: warp w owns queries 2w, 2w+1 (no block syncs inside)
    #pragma unroll
    for (int t = 0; t < 2; t++) {
        int qi = wid * 2 + t, bound = q0 + qi;
        float mx = -1e30f;
        for (int key = lane; key <= bound; key += 32) mx = fmaxf(mx, sc[qi * SLEN + key]);
        #pragma unroll
        for (int o = 16; o; o >>= 1) mx = fmaxf(mx, __shfl_xor_sync(0xffffffffu, mx, o));
        float s = 0.f;
        for (int key = lane; key < nkb; key += 32) {
            float e = (key <= bound) ? expf(sc[qi * SLEN + key] - mx) : 0.f;
            sc[qi * SLEN + key] = e; s += e;
        }
        #pragma unroll
        for (int o = 16; o; o >>= 1) s += __shfl_xor_sync(0xffffffffu, s, o);
        if (lane == 0) sinv[qi] = 1.0f / s;
    }
    __syncthreads();

    // ctx = softmax @ V, V staged through smem
    const int d = tid & 63, half = tid >> 6;
    const float* vb = qkv + rb + 2 * D;
    float a[QT];
    #pragma unroll
    for (int qi = 0; qi < QT; qi++) a[qi] = 0.f;
    for (int c0 = 0; c0 < nkb; c0 += KCH) {
        int rows = nkb - c0; if (rows > KCH) rows = KCH;
        for (int idx = tid; idx < rows * 16; idx += 128) {
            int r = idx >> 4, c4 = (idx & 15) * 4;
            float4 v = *(const float4*)(vb + (size_t)(c0 + r) * K3D + c4);
            sk[r * 65 + c4 + 0] = v.x; sk[r * 65 + c4 + 1] = v.y;
            sk[r * 65 + c4 + 2] = v.z; sk[r * 65 + c4 + 3] = v.w;
        }
        __syncthreads();
        for (int key = half; key < rows; key += 2) {
            float vv = sk[key * 65 + d];
            #pragma unroll
            for (int qi = 0; qi < QT; qi++)
                a[qi] = fmaf(sc[qi * SLEN + c0 + key], vv, a[qi]);
        }
        __syncthreads();
    }
    // combine halves via smem (reuse sk)
    for (int qi = 0; qi < QT; qi++) {
        sk[tid] = a[qi]; __syncthreads();
        if (tid < 64) {
            float v = (sk[tid] + sk[tid + 64]) * sinv[qi];
            size_t row = (size_t)(bb * SLEN + q0 + qi);
            __nv_bfloat16 hi, lo; split2(v, hi, lo);
            a3[row * 2 * D + hd * DH + d] = hi;
            a3[row * 2 * D + D + hd * DH + d] = lo;
        }
        __syncthreads();
    }
}

// ---------------- launcher ----------------
extern "C" void kernel_launch(void* const* d_in, const int* in_sizes, int n_in,
                              void* d_out, int out_size) {
    const int*   x   = (const int*)  d_in[0];
    const int*   len = (const int*)  d_in[1];
    const float* tok = (const float*)d_in[2];
    const float* pos = (const float*)d_in[3];
    const float* leg = (const float*)d_in[4];
    const float* leb = (const float*)d_in[5];
    const float* Wq = (const float*)d_in[6];  const float* bq = (const float*)d_in[7];
    const float* Wk = (const float*)d_in[8];  const float* bk = (const float*)d_in[9];
    const float* Wv = (const float*)d_in[10]; const float* bv = (const float*)d_in[11];
    const float* Wo = (const float*)d_in[12]; const float* bo = (const float*)d_in[13];
    const float* l1g = (const float*)d_in[14]; const float* l1b = (const float*)d_in[15];
    const float* W1 = (const float*)d_in[16]; const float* b1 = (const float*)d_in[17];
    const float* W2 = (const float*)d_in[18]; const float* b2 = (const float*)d_in[19];
    const float* l2g = (const float*)d_in[20]; const float* l2b = (const float*)d_in[21];
    const float* pW = (const float*)d_in[22]; const float* pb = (const float*)d_in[23];
    float* out = (float*)d_out;

    float *h, *qkv, *tmp, *bqkv;
    __nv_bfloat16 *a3, *s2, *wqkv, *wo, *w1, *w2, *wp;
    cudaGetSymbolAddress((void**)&h, g_h);     cudaGetSymbolAddress((void**)&qkv, g_qkv);
    cudaGetSymbolAddress((void**)&tmp, g_tmp); cudaGetSymbolAddress((void**)&bqkv, g_bqkv);
    cudaGetSymbolAddress((void**)&a3, g_a3);   cudaGetSymbolAddress((void**)&s2, g_s2);
    cudaGetSymbolAddress((void**)&wqkv, g_wqkv); cudaGetSymbolAddress((void**)&wo, g_wo);
    cudaGetSymbolAddress((void**)&w1, g_w1);   cudaGetSymbolAddress((void**)&w2, g_w2);
    cudaGetSymbolAddress((void**)&wp, g_wp);

    const int sm2 = NSTG * (128 + 128) * 144;
    const int sm4 = NSTG * (128 + 256) * 144;
    cudaFuncSetAttribute(gemm_kernel<2>, cudaFuncAttributeMaxDynamicSharedMemorySize, sm2);
    cudaFuncSetAttribute(gemm_kernel<4>, cudaFuncAttributeMaxDynamicSharedMemorySize, sm4);
    cudaFuncSetAttribute(attn_kernel, cudaFuncAttributeMaxDynamicSharedMemorySize, ATTN_SMEM);

    for (int i = 0; i < LYRS; i++) {
        size_t w = (size_t)i * D * D;
        __nv_bfloat16* wq3 = wqkv + (size_t)i * K3D * 2 * D;
        convert_w<<<dim3(D/32, D/32), 256>>>(Wq + w, wq3, D, D, 0,   2*D);
        convert_w<<<dim3(D/32, D/32), 256>>>(Wk + w, wq3, D, D, D,   2*D);
        convert_w<<<dim3(D/32, D/32), 256>>>(Wv + w, wq3, D, D, 2*D, 2*D);
        convert_w<<<dim3(D/32, D/32), 256>>>(Wo + w, wo + (size_t)i*D*2*D, D, D, 0, 2*D);
        convert_w<<<dim3(D/32, FF/32), 256>>>(W1 + (size_t)i*D*FF, w1 + (size_t)i*FF*2*D, D, FF, 0, 2*D);
        convert_w<<<dim3(FF/32, D/32), 256>>>(W2 + (size_t)i*FF*D, w2 + (size_t)i*D*2*FF, FF, D, 0, 2*FF);
        concat_bias<<<4, 256>>>(bq + (size_t)i*D, bk + (size_t)i*D, bv + (size_t)i*D, bqkv + (size_t)i*K3D);
    }
    convert_w<<<dim3(D/32, V/32), 256>>>(pW, wp, D, V, 0, 2*D);

    embed_ln_kernel<<<TOK, 256>>>(x, len, tok, pos, leg, leb, h, a3);

    for (int i = 0; i < LYRS; i++) {
        gemm_kernel<4><<<dim3(TOK/128, K3D/256), 256, sm4>>>(
            a3, wqkv + (size_t)i*K3D*2*D, bqkv + (size_t)i*K3D, qkv, (__nv_bfloat16*)0, D, K3D, 0);

        attn_kernel<<<dim3(SLEN/QT, H, BS), 128, ATTN_SMEM>>>(qkv, a3);

        gemm_kernel<2><<<dim3(TOK/128, D/128), 128, sm2>>>(
            a3, wo + (size_t)i*D*2*D, bo + (size_t)i*D, tmp, (__nv_bfloat16*)0, D, D, 0);
        add_ln_kernel<<<TOK, 256>>>(h, tmp, l1g + (size_t)i*D, l1b + (size_t)i*D, (const int*)0, h, a3);

        gemm_kernel<4><<<dim3(TOK/128, FF/256), 256, sm4>>>(
            a3, w1 + (size_t)i*FF*2*D, b1 + (size_t)i*FF, (float*)0, s2, D, FF, 1);

        gemm_kernel<2><<<dim3(TOK/128, D/128), 128, sm2>>>(
            s2, w2 + (size_t)i*D*2*FF, b2 + (size_t)i*D, tmp, (__nv_bfloat16*)0, FF, D, 0);
        add_ln_kernel<<<TOK, 256>>>(h, tmp, l2g + (size_t)i*D, l2b + (size_t)i*D, len, h, a3);
    }

    gemm_kernel<4><<<dim3(TOK/128, V/256), 256, sm4>>>(
        a3, wp, pb, out, (__nv_bfloat16*)0, D, V, 0);
}

// round 7
// speedup vs baseline: 4.2815x; 1.1447x over previous
#include <cuda_runtime.h>
#include <cuda_bf16.h>
#include <math.h>
#include <stdint.h>

#define LYRS 2
#define H 16
#define D 1024
#define DH 64
#define FF 4096
#define V 32000
#define SLEN 1024
#define BS 2
#define TOK (BS*SLEN)
#define EPS 1e-12f
#define K3D (3*D)
#define NSTG 4

// ---------------- scratch ----------------
__device__ float g_h  [TOK*D];
__device__ float g_qkv[TOK*K3D];
__device__ float g_tmp[TOK*D];
__device__ float g_bqkv[LYRS*K3D];
// bf16 operand buffers: tiled layout [rowTile128][kChunk64][128x64 swizzled 16KB]
__device__ __align__(256) __nv_bfloat16 g_a3 [TOK*2*D];
__device__ __align__(256) __nv_bfloat16 g_s2 [TOK*2*FF];
__device__ __align__(256) __nv_bfloat16 g_wqkv[LYRS*(size_t)K3D*2*D];
__device__ __align__(256) __nv_bfloat16 g_wo  [LYRS*(size_t)D*2*D];
__device__ __align__(256) __nv_bfloat16 g_w1  [LYRS*(size_t)FF*2*D];
__device__ __align__(256) __nv_bfloat16 g_w2  [LYRS*(size_t)D*2*FF];
__device__ __align__(256) __nv_bfloat16 g_wp  [(size_t)V*2*D];

// ---------------- helpers ----------------
__device__ __forceinline__ uint32_t s2u(const void* p) {
    uint32_t a;
    asm("{ .reg .u64 t; cvta.to.shared.u64 t, %1; cvt.u32.u64 %0, t; }" : "=r"(a) : "l"(p));
    return a;
}
#define SWZ(o) ((o) ^ (((o) >> 3) & 0x70))
__device__ __forceinline__ void mbar_init(uint32_t a, uint32_t c) {
    asm volatile("mbarrier.init.shared.b64 [%0], %1;" :: "r"(a), "r"(c) : "memory");
}
__device__ __forceinline__ void mbar_expect(uint32_t a, uint32_t tx) {
    asm volatile("mbarrier.arrive.expect_tx.shared.b64 _, [%0], %1;" :: "r"(a), "r"(tx) : "memory");
}
__device__ __forceinline__ void mbar_wait(uint32_t a, uint32_t ph) {
    asm volatile(
        "{\n\t.reg .pred P;\n\tL_%=:\n\t"
        "mbarrier.try_wait.parity.acquire.cta.shared::cta.b64 P, [%0], %1, 0x989680;\n\t"
        "@P bra D_%=;\n\tbra L_%=;\n\tD_%=:\n\t}" :: "r"(a), "r"(ph) : "memory");
}
__device__ __forceinline__ void bulk_ld(uint32_t dst, const void* src, uint32_t bytes, uint32_t mbar) {
    asm volatile("cp.async.bulk.shared::cta.global.mbarrier::complete_tx::bytes [%0], [%1], %2, [%3];"
                 :: "r"(dst), "l"(src), "r"(bytes), "r"(mbar) : "memory");
}
__device__ __forceinline__ void ldm4(uint32_t (&r)[4], uint32_t addr) {
    asm volatile("ldmatrix.sync.aligned.m8n8.x4.shared.b16 {%0,%1,%2,%3}, [%4];"
                 : "=r"(r[0]), "=r"(r[1]), "=r"(r[2]), "=r"(r[3]) : "r"(addr));
}
__device__ __forceinline__ void mma16816(float (&c)[4], const uint32_t a0, const uint32_t a1,
                                         const uint32_t a2, const uint32_t a3,
                                         const uint32_t b0, const uint32_t b1) {
    asm volatile("mma.sync.aligned.m16n8k16.row.col.f32.bf16.bf16.f32 "
                 "{%0,%1,%2,%3}, {%4,%5,%6,%7}, {%8,%9}, {%0,%1,%2,%3};"
                 : "+f"(c[0]), "+f"(c[1]), "+f"(c[2]), "+f"(c[3])
                 : "r"(a0), "r"(a1), "r"(a2), "r"(a3), "r"(b0), "r"(b1));
}
__device__ __forceinline__ void split2(float v, __nv_bfloat16& hi, __nv_bfloat16& lo) {
    hi = __float2bfloat16(v);
    lo = __float2bfloat16(v - __bfloat162float(hi));
}
// store one bf16 element into tiled+swizzled layout; nch = total 64-col chunks of buffer
__device__ __forceinline__ void store_elem(__nv_bfloat16* buf, int nch, int row, int k, __nv_bfloat16 v) {
    int t = row >> 7, rr = row & 127, c = k >> 6, kk = k & 63;
    uint32_t off = SWZ((uint32_t)(rr * 128 + kk * 2));
    *(__nv_bfloat16*)((char*)buf + (((size_t)(t * nch + c)) << 14) + off) = v;
}

// ---------------- weight conversion: W[K,N] f32 -> tiled [hi|lo] rows ----------------
__global__ void convert_w(const float* __restrict__ W, __nv_bfloat16* __restrict__ out,
                          int K, int N, int rowOff) {
    __shared__ float t[32][33];
    int k0 = blockIdx.x * 32, n0 = blockIdx.y * 32;
    int tx = threadIdx.x & 31, ty = threadIdx.x >> 5;
    int nch = K >> 5;
    #pragma unroll
    for (int i = 0; i < 4; i++)
        t[ty + i * 8][tx] = W[(size_t)(k0 + ty + i * 8) * N + n0 + tx];
    __syncthreads();
    #pragma unroll
    for (int i = 0; i < 4; i++) {
        int n = rowOff + n0 + ty + i * 8, k = k0 + tx;
        __nv_bfloat16 hi, lo;
        split2(t[tx][ty + i * 8], hi, lo);
        store_elem(out, nch, n, k, hi);
        store_elem(out, nch, n, K + k, lo);
    }
}
__global__ void concat_bias(const float* __restrict__ a, const float* __restrict__ b,
                            const float* __restrict__ c, float* __restrict__ o) {
    int i = blockIdx.x * 256 + threadIdx.x;
    if (i < D) { o[i] = a[i]; o[D + i] = b[i]; o[2 * D + i] = c[i]; }
}

// ---------------- GEMM: C[2048,N] = A @ B^T, bf16x3 3-phase, TMA bulk loads ----
// NB = number of 128-row B tiles per CTA. Warps 2(M) x 2NB(N), warp tile 64x64.
template<int NB>
__global__ void __launch_bounds__(128*NB, 1) gemm_kernel(
    const __nv_bfloat16* __restrict__ A, const __nv_bfloat16* __restrict__ B,
    const float* __restrict__ bias, float* __restrict__ C, __nv_bfloat16* __restrict__ S,
    int Kp, int N, int act)
{
    constexpr int STG = (1 + NB) * 16384;
    extern __shared__ __align__(128) char smem[];
    const int tid = threadIdx.x, wid = tid >> 5, lane = tid & 31;
    const int wm = wid & 1, wn = wid >> 1;
    const int m0 = blockIdx.x * 128, n0 = blockIdx.y * NB * 128;
    const uint32_t sb = s2u(smem);
    const uint32_t MB = sb + NSTG * STG;
    const int nch0 = Kp / 64, nch = 3 * nch0, nchT = 2 * nch0;

    if (tid == 0) {
        #pragma unroll
        for (int s = 0; s < NSTG; s++) mbar_init(MB + 8 * s, 1);
    }
    __syncthreads();

    auto issue = [&](int c) {
        int p = c / nch0, kk = c - p * nch0;
        int ac = ((p == 2) ? nch0 : 0) + kk;
        int bc = ((p == 1) ? nch0 : 0) + kk;
        int s = c & (NSTG - 1);
        uint32_t mb = MB + 8 * s, dst = sb + s * STG;
        mbar_expect(mb, (1 + NB) * 16384);
        bulk_ld(dst, (const char*)A + (((size_t)(blockIdx.x * nchT + ac)) << 14), 16384, mb);
        #pragma unroll
        for (int t = 0; t < NB; t++)
            bulk_ld(dst + 16384 + t * 16384,
                    (const char*)B + (((size_t)((blockIdx.y * NB + t) * nchT + bc)) << 14), 16384, mb);
    };
    if (tid == 0) { issue(0); issue(1); issue(2); }

    float acc[4][8][4];
    #pragma unroll
    for (int mi = 0; mi < 4; mi++)
        #pragma unroll
        for (int ni = 0; ni < 8; ni++)
            #pragma unroll
            for (int j = 0; j < 4; j++) acc[mi][ni][j] = 0.f;

    const int lq = lane & 7, lh = (lane >> 3) & 1, lk = lane >> 4;

    for (int c = 0; c < nch; c++) {
        mbar_wait(MB + 8 * (c & (NSTG - 1)), (c >> 2) & 1);
        uint32_t stg = sb + (c & (NSTG - 1)) * STG;
        uint32_t bstg = stg + 16384 + (wn >> 1) * 16384;
        #pragma unroll
        for (int ks = 0; ks < 4; ks++) {
            uint32_t af[4][4], bf[4][4];
            #pragma unroll
            for (int mt = 0; mt < 4; mt++) {
                int r = wm * 64 + mt * 16 + lh * 8 + lq;
                ldm4(af[mt], stg + r * 128 + (((ks * 2 + lk) ^ (r & 7)) << 4));
            }
            #pragma unroll
            for (int nt = 0; nt < 4; nt++) {
                int r = (wn & 1) * 64 + nt * 16 + lh * 8 + lq;
                ldm4(bf[nt], bstg + r * 128 + (((ks * 2 + lk) ^ (r & 7)) << 4));
            }
            #pragma unroll
            for (int mi = 0; mi < 4; mi++)
                #pragma unroll
                for (int ni = 0; ni < 8; ni++) {
                    uint32_t b0 = bf[ni >> 1][ni & 1], b1 = bf[ni >> 1][(ni & 1) + 2];
                    mma16816(acc[mi][ni], af[mi][0], af[mi][1], af[mi][2], af[mi][3], b0, b1);
                }
        }
        __syncthreads();
        if (tid == 0 && c + NSTG - 1 < nch) issue(c + NSTG - 1);
    }

    const int r0 = lane >> 2, cp = (lane & 3) * 2;
    const int nchS = N >> 5;
    #pragma unroll
    for (int mi = 0; mi < 4; mi++) {
        #pragma unroll
        for (int ni = 0; ni < 8; ni++) {
            int col = n0 + wn * 64 + ni * 8 + cp;
            float bb0 = bias[col], bb1 = bias[col + 1];
            #pragma unroll
            for (int half = 0; half < 2; half++) {
                int row = m0 + wm * 64 + mi * 16 + r0 + half * 8;
                float v0 = acc[mi][ni][half * 2 + 0] + bb0;
                float v1 = acc[mi][ni][half * 2 + 1] + bb1;
                if (act) {
                    v0 = 0.5f * v0 * (1.0f + erff(v0 * 0.70710678118654752f));
                    v1 = 0.5f * v1 * (1.0f + erff(v1 * 0.70710678118654752f));
                }
                if (C) {
                    float2 o; o.x = v0; o.y = v1;
                    *(float2*)(C + (size_t)row * N + col) = o;
                }
                if (S) {
                    __nv_bfloat16 h0, l0, h1, l1;
                    split2(v0, h0, l0); split2(v1, h1, l1);
                    int t = row >> 7, rr = row & 127;
                    // hi pair at col
                    uint32_t offh = SWZ((uint32_t)(rr * 128 + (col & 63) * 2));
                    __nv_bfloat162 hp; hp.x = h0; hp.y = h1;
                    *(__nv_bfloat162*)((char*)S + (((size_t)(t * nchS + (col >> 6))) << 14) + offh) = hp;
                    // lo pair at N+col
                    __nv_bfloat162 lp; lp.x = l0; lp.y = l1;
                    *(__nv_bfloat162*)((char*)S + (((size_t)(t * nchS + ((N + col) >> 6))) << 14) + offh) = lp;
                }
            }
        }
    }
}

// ---------------- LayerNorm ----------------
__device__ __forceinline__ float brsum(float v, float* sbuf) {
    int tid = threadIdx.x;
    #pragma unroll
    for (int o = 16; o; o >>= 1) v += __shfl_down_sync(0xffffffffu, v, o);
    if ((tid & 31) == 0) sbuf[tid >> 5] = v;
    __syncthreads();
    if (tid < 8) {
        v = sbuf[tid];
        #pragma unroll
        for (int o = 4; o; o >>= 1) v += __shfl_down_sync(0xffu, v, o);
        if (tid == 0) sbuf[0] = v;
    }
    __syncthreads();
    float r = sbuf[0];
    __syncthreads();
    return r;
}
__global__ void embed_ln_kernel(const int* __restrict__ x, const int* __restrict__ len,
                                const float* __restrict__ tok, const float* __restrict__ pos,
                                const float* __restrict__ g, const float* __restrict__ b,
                                float* __restrict__ out, __nv_bfloat16* __restrict__ sp) {
    int row = blockIdx.x, bi = row / SLEN, s = row % SLEN, token = x[row], tid = threadIdx.x;
    __shared__ float buf[D]; __shared__ float red[8];
    float ls = 0.f;
    #pragma unroll
    for (int i = 0; i < 4; i++) {
        int c = tid + i * 256;
        float v = tok[(size_t)token * D + c] + pos[(size_t)s * D + c];
        buf[c] = v; ls += v;
    }
    float mean = brsum(ls, red) * (1.0f / D), ss = 0.f;
    #pragma unroll
    for (int i = 0; i < 4; i++) { float d = buf[tid + i * 256] - mean; ss += d * d; }
    float rstd = rsqrtf(brsum(ss, red) * (1.0f / D) + EPS);
    float mask = (s < len[bi]) ? 1.0f : 0.0f;
    #pragma unroll
    for (int i = 0; i < 4; i++) {
        int c = tid + i * 256;
        float v = (g[c] * (buf[c] - mean) * rstd + b[c]) * mask;
        out[(size_t)row * D + c] = v;
        __nv_bfloat16 hi, lo; split2(v, hi, lo);
        store_elem(sp, 32, row, c, hi);
        store_elem(sp, 32, row, D + c, lo);
    }
}
__global__ void add_ln_kernel(const float* __restrict__ a, const float* __restrict__ dl,
                              const float* __restrict__ g, const float* __restrict__ b,
                              const int* __restrict__ len, float* __restrict__ out,
                              __nv_bfloat16* __restrict__ sp) {
    int row = blockIdx.x, bi = row / SLEN, s = row % SLEN, tid = threadIdx.x;
    __shared__ float buf[D]; __shared__ float red[8];
    float ls = 0.f;
    #pragma unroll
    for (int i = 0; i < 4; i++) {
        int c = tid + i * 256;
        float v = a[(size_t)row * D + c] + dl[(size_t)row * D + c];
        buf[c] = v; ls += v;
    }
    float mean = brsum(ls, red) * (1.0f / D), ss = 0.f;
    #pragma unroll
    for (int i = 0; i < 4; i++) { float d = buf[tid + i * 256] - mean; ss += d * d; }
    float rstd = rsqrtf(brsum(ss, red) * (1.0f / D) + EPS);
    float mask = len ? ((s < len[bi]) ? 1.0f : 0.0f) : 1.0f;
    #pragma unroll
    for (int i = 0; i < 4; i++) {
        int c = tid + i * 256;
        float v = (g[c] * (buf[c] - mean) * rstd + b[c]) * mask;
        out[(size_t)row * D + c] = v;
        __nv_bfloat16 hi, lo; split2(v, hi, lo);
        store_elem(sp, 32, row, c, hi);
        store_elem(sp, 32, row, D + c, lo);
    }
}

// ---------------- attention: 8 q/block, smem-staged K/V, warp softmax ----
#define QT 8
#define KCH 128
#define ATTN_SMEM ((QT*DH + QT*SLEN + KCH*65 + QT) * 4)
__global__ void attn_kernel(const float* __restrict__ qkv, __nv_bfloat16* __restrict__ a3) {
    extern __shared__ float sm[];
    float* sq = sm;
    float* sc = sq + QT * DH;
    float* sk = sc + QT * SLEN;
    float* sinv = sk + KCH * 65;
    const int q0 = blockIdx.x * QT, hd = blockIdx.y, bb = blockIdx.z, tid = threadIdx.x;
    const int wid = tid >> 5, lane = tid & 31;
    const int nkb = q0 + QT;
    const size_t rb = (size_t)(bb * SLEN) * K3D + (size_t)hd * DH;

    for (int i = tid; i < QT * DH; i += 128)
        sq[i] = qkv[rb + (size_t)(q0 + i / DH) * K3D + (i % DH)] * 0.125f;
    __syncthreads();

    const float* kb = qkv + rb + D;
    for (int c0 = 0; c0 < nkb; c0 += KCH) {
        int rows = nkb - c0; if (rows > KCH) rows = KCH;
        for (int idx = tid; idx < rows * 16; idx += 128) {
            int r = idx >> 4, c4 = (idx & 15) * 4;
            float4 v = *(const float4*)(kb + (size_t)(c0 + r) * K3D + c4);
            sk[r * 65 + c4 + 0] = v.x; sk[r * 65 + c4 + 1] = v.y;
            sk[r * 65 + c4 + 2] = v.z; sk[r * 65 + c4 + 3] = v.w;
        }
        __syncthreads();
        for (int key = tid; key < rows; key += 128) {
            float a[QT];
            #pragma unroll
            for (int qi = 0; qi < QT; qi++) a[qi] = 0.f;
            #pragma unroll 8
            for (int d = 0; d < DH; d++) {
                float kd = sk[key * 65 + d];
                #pragma unroll
                for (int qi = 0; qi < QT; qi++) a[qi] = fmaf(sq[qi * DH + d], kd, a[qi]);
            }
            #pragma unroll
            for (int qi = 0; qi < QT; qi++) sc[qi * SLEN + c0 + key] = a[qi];
        }
        __syncthreads();
    }

    #pragma unroll
    for (int t = 0; t < 2; t++) {
        int qi = wid * 2 + t, bound = q0 + qi;
        float mx = -1e30f;
        for (int key = lane; key <= bound; key += 32) mx = fmaxf(mx, sc[qi * SLEN + key]);
        #pragma unroll
        for (int o = 16; o; o >>= 1) mx = fmaxf(mx, __shfl_xor_sync(0xffffffffu, mx, o));
        float s = 0.f;
        for (int key = lane; key < nkb; key += 32) {
            float e = (key <= bound) ? expf(sc[qi * SLEN + key] - mx) : 0.f;
            sc[qi * SLEN + key] = e; s += e;
        }
        #pragma unroll
        for (int o = 16; o; o >>= 1) s += __shfl_xor_sync(0xffffffffu, s, o);
        if (lane == 0) sinv[qi] = 1.0f / s;
    }
    __syncthreads();

    const int d = tid & 63, half = tid >> 6;
    const float* vb = qkv + rb + 2 * D;
    float a[QT];
    #pragma unroll
    for (int qi = 0; qi < QT; qi++) a[qi] = 0.f;
    for (int c0 = 0; c0 < nkb; c0 += KCH) {
        int rows = nkb - c0; if (rows > KCH) rows = KCH;
        for (int idx = tid; idx < rows * 16; idx += 128) {
            int r = idx >> 4, c4 = (idx & 15) * 4;
            float4 v = *(const float4*)(vb + (size_t)(c0 + r) * K3D + c4);
            sk[r * 65 + c4 + 0] = v.x; sk[r * 65 + c4 + 1] = v.y;
            sk[r * 65 + c4 + 2] = v.z; sk[r * 65 + c4 + 3] = v.w;
        }
        __syncthreads();
        for (int key = half; key < rows; key += 2) {
            float vv = sk[key * 65 + d];
            #pragma unroll
            for (int qi = 0; qi < QT; qi++)
                a[qi] = fmaf(sc[qi * SLEN + c0 + key], vv, a[qi]);
        }
        __syncthreads();
    }
    for (int qi = 0; qi < QT; qi++) {
        sk[tid] = a[qi]; __syncthreads();
        if (tid < 64) {
            float v = (sk[tid] + sk[tid + 64]) * sinv[qi];
            int row = bb * SLEN + q0 + qi;
            __nv_bfloat16 hi, lo; split2(v, hi, lo);
            store_elem(a3, 32, row, hd * DH + d, hi);
            store_elem(a3, 32, row, D + hd * DH + d, lo);
        }
        __syncthreads();
    }
}

// ---------------- launcher ----------------
extern "C" void kernel_launch(void* const* d_in, const int* in_sizes, int n_in,
                              void* d_out, int out_size) {
    const int*   x   = (const int*)  d_in[0];
    const int*   len = (const int*)  d_in[1];
    const float* tok = (const float*)d_in[2];
    const float* pos = (const float*)d_in[3];
    const float* leg = (const float*)d_in[4];
    const float* leb = (const float*)d_in[5];
    const float* Wq = (const float*)d_in[6];  const float* bq = (const float*)d_in[7];
    const float* Wk = (const float*)d_in[8];  const float* bk = (const float*)d_in[9];
    const float* Wv = (const float*)d_in[10]; const float* bv = (const float*)d_in[11];
    const float* Wo = (const float*)d_in[12]; const float* bo = (const float*)d_in[13];
    const float* l1g = (const float*)d_in[14]; const float* l1b = (const float*)d_in[15];
    const float* W1 = (const float*)d_in[16]; const float* b1 = (const float*)d_in[17];
    const float* W2 = (const float*)d_in[18]; const float* b2 = (const float*)d_in[19];
    const float* l2g = (const float*)d_in[20]; const float* l2b = (const float*)d_in[21];
    const float* pW = (const float*)d_in[22]; const float* pb = (const float*)d_in[23];
    float* out = (float*)d_out;

    float *h, *qkv, *tmp, *bqkv;
    __nv_bfloat16 *a3, *s2, *wqkv, *wo, *w1, *w2, *wp;
    cudaGetSymbolAddress((void**)&h, g_h);     cudaGetSymbolAddress((void**)&qkv, g_qkv);
    cudaGetSymbolAddress((void**)&tmp, g_tmp); cudaGetSymbolAddress((void**)&bqkv, g_bqkv);
    cudaGetSymbolAddress((void**)&a3, g_a3);   cudaGetSymbolAddress((void**)&s2, g_s2);
    cudaGetSymbolAddress((void**)&wqkv, g_wqkv); cudaGetSymbolAddress((void**)&wo, g_wo);
    cudaGetSymbolAddress((void**)&w1, g_w1);   cudaGetSymbolAddress((void**)&w2, g_w2);
    cudaGetSymbolAddress((void**)&wp, g_wp);

    const int sm1 = NSTG * 2 * 16384 + 64;   // NB=1: 131136
    const int sm2 = NSTG * 3 * 16384 + 64;   // NB=2: 196672
    cudaFuncSetAttribute(gemm_kernel<1>, cudaFuncAttributeMaxDynamicSharedMemorySize, sm1);
    cudaFuncSetAttribute(gemm_kernel<2>, cudaFuncAttributeMaxDynamicSharedMemorySize, sm2);
    cudaFuncSetAttribute(attn_kernel, cudaFuncAttributeMaxDynamicSharedMemorySize, ATTN_SMEM);

    // L0 QKV weights first so the profiled launch (#5, 0-indexed) is the QKV GEMM
    convert_w<<<dim3(D/32, D/32), 256>>>(Wq, wqkv, D, D, 0);
    convert_w<<<dim3(D/32, D/32), 256>>>(Wk, wqkv, D, D, D);
    convert_w<<<dim3(D/32, D/32), 256>>>(Wv, wqkv, D, D, 2*D);
    concat_bias<<<4, 256>>>(bq, bk, bv, bqkv);
    embed_ln_kernel<<<TOK, 256>>>(x, len, tok, pos, leg, leb, h, a3);
    gemm_kernel<2><<<dim3(TOK/128, K3D/256), 256, sm2>>>(
        a3, wqkv, bqkv, qkv, (__nv_bfloat16*)0, D, K3D, 0);

    // remaining conversions
    convert_w<<<dim3(D/32, D/32), 256>>>(Wo, wo, D, D, 0);
    convert_w<<<dim3(D/32, FF/32), 256>>>(W1, w1, D, FF, 0);
    convert_w<<<dim3(FF/32, D/32), 256>>>(W2, w2, FF, D, 0);
    {
        size_t w = (size_t)D * D;
        __nv_bfloat16* wq3 = wqkv + (size_t)K3D * 2 * D;
        convert_w<<<dim3(D/32, D/32), 256>>>(Wq + w, wq3, D, D, 0);
        convert_w<<<dim3(D/32, D/32), 256>>>(Wk + w, wq3, D, D, D);
        convert_w<<<dim3(D/32, D/32), 256>>>(Wv + w, wq3, D, D, 2*D);
        convert_w<<<dim3(D/32, D/32), 256>>>(Wo + w, wo + (size_t)D*2*D, D, D, 0);
        convert_w<<<dim3(D/32, FF/32), 256>>>(W1 + (size_t)D*FF, w1 + (size_t)FF*2*D, D, FF, 0);
        convert_w<<<dim3(FF/32, D/32), 256>>>(W2 + (size_t)FF*D, w2 + (size_t)D*2*FF, FF, D, 0);
        concat_bias<<<4, 256>>>(bq + D, bk + D, bv + D, bqkv + K3D);
    }
    convert_w<<<dim3(D/32, V/32), 256>>>(pW, wp, D, V, 0);

    for (int i = 0; i < LYRS; i++) {
        if (i > 0)
            gemm_kernel<2><<<dim3(TOK/128, K3D/256), 256, sm2>>>(
                a3, wqkv + (size_t)i*K3D*2*D, bqkv + (size_t)i*K3D, qkv, (__nv_bfloat16*)0, D, K3D, 0);

        attn_kernel<<<dim3(SLEN/QT, H, BS), 128, ATTN_SMEM>>>(qkv, a3);

        gemm_kernel<1><<<dim3(TOK/128, D/128), 128, sm1>>>(
            a3, wo + (size_t)i*D*2*D, bo + (size_t)i*D, tmp, (__nv_bfloat16*)0, D, D, 0);
        add_ln_kernel<<<TOK, 256>>>(h, tmp, l1g + (size_t)i*D, l1b + (size_t)i*D, (const int*)0, h, a3);

        gemm_kernel<2><<<dim3(TOK/128, FF/256), 256, sm2>>>(
            a3, w1 + (size_t)i*FF*2*D, b1 + (size_t)i*FF, (float*)0, s2, D, FF, 1);

        gemm_kernel<1><<<dim3(TOK/128, D/128), 128, sm1>>>(
            s2, w2 + (size_t)i*D*2*FF, b2 + (size_t)i*D, tmp, (__nv_bfloat16*)0, FF, D, 0);
        add_ln_kernel<<<TOK, 256>>>(h, tmp, l2g + (size_t)i*D, l2b + (size_t)i*D, len, h, a3);
    }

    gemm_kernel<2><<<dim3(TOK/128, V/256), 256, sm2>>>(
        a3, wp, pb, out, (__nv_bfloat16*)0, D, V, 0);
}

// round 8
// speedup vs baseline: 5.6459x; 1.3187x over previous
#include <cuda_runtime.h>
#include <cuda_fp16.h>
#include <math.h>
#include <stdint.h>

#define LYRS 2
#define H 16
#define D 1024
#define DH 64
#define FF 4096
#define V 32000
#define SLEN 1024
#define BS 2
#define TOK (BS*SLEN)
#define EPS 1e-12f
#define K3D (3*D)
#define NSTG 3

// ---------------- scratch ----------------
__device__ float g_h  [TOK*D];
__device__ float g_qkv[TOK*K3D];
__device__ float g_tmp[TOK*D];
__device__ float g_bqkv[LYRS*K3D];
// fp16 operand buffers, tiled layout [rowTile128][kChunk64][128x64 swizzled 16KB]
// A-side buffers hold [hi|lo] (2K extent); weight buffers hold single fp16 (K extent)
__device__ __align__(256) __half g_a3 [TOK*2*D];
__device__ __align__(256) __half g_s2 [TOK*2*FF];
__device__ __align__(256) __half g_wqkv[LYRS*(size_t)K3D*D];
__device__ __align__(256) __half g_wo  [LYRS*(size_t)D*D];
__device__ __align__(256) __half g_w1  [LYRS*(size_t)FF*D];
__device__ __align__(256) __half g_w2  [LYRS*(size_t)D*FF];
__device__ __align__(256) __half g_wp  [(size_t)V*D];

// ---------------- helpers ----------------
__device__ __forceinline__ uint32_t s2u(const void* p) {
    uint32_t a;
    asm("{ .reg .u64 t; cvta.to.shared.u64 t, %1; cvt.u32.u64 %0, t; }" : "=r"(a) : "l"(p));
    return a;
}
#define SWZ(o) ((o) ^ (((o) >> 3) & 0x70))
__device__ __forceinline__ void mbar_init(uint32_t a, uint32_t c) {
    asm volatile("mbarrier.init.shared.b64 [%0], %1;" :: "r"(a), "r"(c) : "memory");
}
__device__ __forceinline__ void mbar_expect(uint32_t a, uint32_t tx) {
    asm volatile("mbarrier.arrive.expect_tx.shared.b64 _, [%0], %1;" :: "r"(a), "r"(tx) : "memory");
}
__device__ __forceinline__ void mbar_wait(uint32_t a, uint32_t ph) {
    asm volatile(
        "{\n\t.reg .pred P;\n\tL_%=:\n\t"
        "mbarrier.try_wait.parity.acquire.cta.shared::cta.b64 P, [%0], %1, 0x989680;\n\t"
        "@P bra D_%=;\n\tbra L_%=;\n\tD_%=:\n\t}" :: "r"(a), "r"(ph) : "memory");
}
__device__ __forceinline__ void bulk_ld(uint32_t dst, const void* src, uint32_t bytes, uint32_t mbar) {
    asm volatile("cp.async.bulk.shared::cta.global.mbarrier::complete_tx::bytes [%0], [%1], %2, [%3];"
                 :: "r"(dst), "l"(src), "r"(bytes), "r"(mbar) : "memory");
}
__device__ __forceinline__ void ldm4(uint32_t (&r)[4], uint32_t addr) {
    asm volatile("ldmatrix.sync.aligned.m8n8.x4.shared.b16 {%0,%1,%2,%3}, [%4];"
                 : "=r"(r[0]), "=r"(r[1]), "=r"(r[2]), "=r"(r[3]) : "r"(addr));
}
__device__ __forceinline__ void mma16816(float (&c)[4], const uint32_t a0, const uint32_t a1,
                                         const uint32_t a2, const uint32_t a3,
                                         const uint32_t b0, const uint32_t b1) {
    asm volatile("mma.sync.aligned.m16n8k16.row.col.f32.f16.f16.f32 "
                 "{%0,%1,%2,%3}, {%4,%5,%6,%7}, {%8,%9}, {%0,%1,%2,%3};"
                 : "+f"(c[0]), "+f"(c[1]), "+f"(c[2]), "+f"(c[3])
                 : "r"(a0), "r"(a1), "r"(a2), "r"(a3), "r"(b0), "r"(b1));
}
__device__ __forceinline__ void split2(float v, __half& hi, __half& lo) {
    hi = __float2half(v);
    lo = __float2half(v - __half2float(hi));
}
// store one fp16 element into tiled+swizzled layout; nch = total 64-col chunks of buffer
__device__ __forceinline__ void store_elem(__half* buf, int nch, int row, int k, __half v) {
    int t = row >> 7, rr = row & 127, c = k >> 6, kk = k & 63;
    uint32_t off = SWZ((uint32_t)(rr * 128 + kk * 2));
    *(__half*)((char*)buf + (((size_t)(t * nch + c)) << 14) + off) = v;
}

// ---------------- weight conversion: W[K,N] f32 -> tiled fp16 rows ----------------
__global__ void convert_w(const float* __restrict__ W, __half* __restrict__ out,
                          int K, int N, int rowOff) {
    __shared__ float t[32][33];
    int k0 = blockIdx.x * 32, n0 = blockIdx.y * 32;
    int tx = threadIdx.x & 31, ty = threadIdx.x >> 5;
    int nch = K >> 6;
    #pragma unroll
    for (int i = 0; i < 4; i++)
        t[ty + i * 8][tx] = W[(size_t)(k0 + ty + i * 8) * N + n0 + tx];
    __syncthreads();
    #pragma unroll
    for (int i = 0; i < 4; i++) {
        int n = rowOff + n0 + ty + i * 8, k = k0 + tx;
        store_elem(out, nch, n, k, __float2half(t[tx][ty + i * 8]));
    }
}
__global__ void concat_bias(const float* __restrict__ a, const float* __restrict__ b,
                            const float* __restrict__ c, float* __restrict__ o) {
    int i = blockIdx.x * 256 + threadIdx.x;
    if (i < D) { o[i] = a[i]; o[D + i] = b[i]; o[2 * D + i] = c[i]; }
}

// ---------------- GEMM: C[2048,N] = A @ B^T, fp16 2-phase (A=[hi|lo], B=fp16) ----
// Stage = [A_hi 16K][A_lo 16K][B NB*16K]; B loaded once per k-chunk, used by both phases.
// NB = 128-row B tiles per CTA. Warps 2(M) x 2NB(N), warp tile 64x64.
template<int NB>
__global__ void __launch_bounds__(128*NB, 1) gemm_kernel(
    const __half* __restrict__ A, const __half* __restrict__ B,
    const float* __restrict__ bias, float* __restrict__ C, __half* __restrict__ S,
    int Kp, int N, int act)
{
    constexpr int STG = (2 + NB) * 16384;
    extern __shared__ __align__(128) char smem[];
    const int tid = threadIdx.x, wid = tid >> 5, lane = tid & 31;
    const int wm = wid & 1, wn = wid >> 1;
    const int m0 = blockIdx.x * 128, n0 = blockIdx.y * NB * 128;
    const uint32_t sb = s2u(smem);
    const uint32_t MB = sb + NSTG * STG;
    const int nch0 = Kp / 64;

    if (tid == 0) {
        #pragma unroll
        for (int s = 0; s < NSTG; s++) mbar_init(MB + 8 * s, 1);
    }
    __syncthreads();

    auto issue = [&](int kk) {
        int s = kk % NSTG;
        uint32_t mb = MB + 8 * s, dst = sb + s * STG;
        mbar_expect(mb, (2 + NB) * 16384);
        bulk_ld(dst, (const char*)A + (((size_t)(blockIdx.x * 2 * nch0 + kk)) << 14), 16384, mb);
        bulk_ld(dst + 16384, (const char*)A + (((size_t)(blockIdx.x * 2 * nch0 + nch0 + kk)) << 14), 16384, mb);
        #pragma unroll
        for (int t = 0; t < NB; t++)
            bulk_ld(dst + 32768 + t * 16384,
                    (const char*)B + (((size_t)((blockIdx.y * NB + t) * nch0 + kk)) << 14), 16384, mb);
    };
    if (tid == 0) { issue(0); issue(1); issue(2); }

    float acc[4][8][4];
    #pragma unroll
    for (int mi = 0; mi < 4; mi++)
        #pragma unroll
        for (int ni = 0; ni < 8; ni++)
            #pragma unroll
            for (int j = 0; j < 4; j++) acc[mi][ni][j] = 0.f;

    const int lq = lane & 7, lh = (lane >> 3) & 1, lk = lane >> 4;

    for (int kk = 0; kk < nch0; kk++) {
        mbar_wait(MB + 8 * (kk % NSTG), (kk / NSTG) & 1);
        uint32_t stg = sb + (kk % NSTG) * STG;
        uint32_t bstg = stg + 32768 + (wn >> 1) * 16384;
        #pragma unroll
        for (int p = 0; p < 2; p++) {
            uint32_t astg = stg + p * 16384;
            #pragma unroll
            for (int ks = 0; ks < 4; ks++) {
                uint32_t af[4][4], bf[4][4];
                #pragma unroll
                for (int mt = 0; mt < 4; mt++) {
                    int r = wm * 64 + mt * 16 + lh * 8 + lq;
                    ldm4(af[mt], astg + r * 128 + (((ks * 2 + lk) ^ (r & 7)) << 4));
                }
                #pragma unroll
                for (int nt = 0; nt < 4; nt++) {
                    int r = (wn & 1) * 64 + nt * 16 + lh * 8 + lq;
                    ldm4(bf[nt], bstg + r * 128 + (((ks * 2 + lk) ^ (r & 7)) << 4));
                }
                #pragma unroll
                for (int mi = 0; mi < 4; mi++)
                    #pragma unroll
                    for (int ni = 0; ni < 8; ni++) {
                        uint32_t b0 = bf[ni >> 1][ni & 1], b1 = bf[ni >> 1][(ni & 1) + 2];
                        mma16816(acc[mi][ni], af[mi][0], af[mi][1], af[mi][2], af[mi][3], b0, b1);
                    }
            }
        }
        __syncthreads();
        if (tid == 0 && kk + NSTG < nch0) issue(kk + NSTG);
    }

    const int r0 = lane >> 2, cp = (lane & 3) * 2;
    const int nchS = N >> 5;
    #pragma unroll
    for (int mi = 0; mi < 4; mi++) {
        #pragma unroll
        for (int ni = 0; ni < 8; ni++) {
            int col = n0 + wn * 64 + ni * 8 + cp;
            float bb0 = bias[col], bb1 = bias[col + 1];
            #pragma unroll
            for (int half = 0; half < 2; half++) {
                int row = m0 + wm * 64 + mi * 16 + r0 + half * 8;
                float v0 = acc[mi][ni][half * 2 + 0] + bb0;
                float v1 = acc[mi][ni][half * 2 + 1] + bb1;
                if (act) {
                    v0 = 0.5f * v0 * (1.0f + erff(v0 * 0.70710678118654752f));
                    v1 = 0.5f * v1 * (1.0f + erff(v1 * 0.70710678118654752f));
                }
                if (C) {
                    float2 o; o.x = v0; o.y = v1;
                    *(float2*)(C + (size_t)row * N + col) = o;
                }
                if (S) {
                    __half h0, l0, h1, l1;
                    split2(v0, h0, l0); split2(v1, h1, l1);
                    int t = row >> 7, rr = row & 127;
                    uint32_t offh = SWZ((uint32_t)(rr * 128 + (col & 63) * 2));
                    __half2 hp; hp.x = h0; hp.y = h1;
                    *(__half2*)((char*)S + (((size_t)(t * nchS + (col >> 6))) << 14) + offh) = hp;
                    __half2 lp; lp.x = l0; lp.y = l1;
                    *(__half2*)((char*)S + (((size_t)(t * nchS + ((N + col) >> 6))) << 14) + offh) = lp;
                }
            }
        }
    }
}

// ---------------- LayerNorm ----------------
__device__ __forceinline__ float brsum(float v, float* sbuf) {
    int tid = threadIdx.x;
    #pragma unroll
    for (int o = 16; o; o >>= 1) v += __shfl_down_sync(0xffffffffu, v, o);
    if ((tid & 31) == 0) sbuf[tid >> 5] = v;
    __syncthreads();
    if (tid < 8) {
        v = sbuf[tid];
        #pragma unroll
        for (int o = 4; o; o >>= 1) v += __shfl_down_sync(0xffu, v, o);
        if (tid == 0) sbuf[0] = v;
    }
    __syncthreads();
    float r = sbuf[0];
    __syncthreads();
    return r;
}
__global__ void embed_ln_kernel(const int* __restrict__ x, const int* __restrict__ len,
                                const float* __restrict__ tok, const float* __restrict__ pos,
                                const float* __restrict__ g, const float* __restrict__ b,
                                float* __restrict__ out, __half* __restrict__ sp) {
    int row = blockIdx.x, bi = row / SLEN, s = row % SLEN, token = x[row], tid = threadIdx.x;
    __shared__ float buf[D]; __shared__ float red[8];
    float ls = 0.f;
    #pragma unroll
    for (int i = 0; i < 4; i++) {
        int c = tid + i * 256;
        float v = tok[(size_t)token * D + c] + pos[(size_t)s * D + c];
        buf[c] = v; ls += v;
    }
    float mean = brsum(ls, red) * (1.0f / D), ss = 0.f;
    #pragma unroll
    for (int i = 0; i < 4; i++) { float d = buf[tid + i * 256] - mean; ss += d * d; }
    float rstd = rsqrtf(brsum(ss, red) * (1.0f / D) + EPS);
    float mask = (s < len[bi]) ? 1.0f : 0.0f;
    #pragma unroll
    for (int i = 0; i < 4; i++) {
        int c = tid + i * 256;
        float v = (g[c] * (buf[c] - mean) * rstd + b[c]) * mask;
        out[(size_t)row * D + c] = v;
        __half hi, lo; split2(v, hi, lo);
        store_elem(sp, 32, row, c, hi);
        store_elem(sp, 32, row, D + c, lo);
    }
}
__global__ void add_ln_kernel(const float* __restrict__ a, const float* __restrict__ dl,
                              const float* __restrict__ g, const float* __restrict__ b,
                              const int* __restrict__ len, float* __restrict__ out,
                              __half* __restrict__ sp) {
    int row = blockIdx.x, bi = row / SLEN, s = row % SLEN, tid = threadIdx.x;
    __shared__ float buf[D]; __shared__ float red[8];
    float ls = 0.f;
    #pragma unroll
    for (int i = 0; i < 4; i++) {
        int c = tid + i * 256;
        float v = a[(size_t)row * D + c] + dl[(size_t)row * D + c];
        buf[c] = v; ls += v;
    }
    float mean = brsum(ls, red) * (1.0f / D), ss = 0.f;
    #pragma unroll
    for (int i = 0; i < 4; i++) { float d = buf[tid + i * 256] - mean; ss += d * d; }
    float rstd = rsqrtf(brsum(ss, red) * (1.0f / D) + EPS);
    float mask = len ? ((s < len[bi]) ? 1.0f : 0.0f) : 1.0f;
    #pragma unroll
    for (int i = 0; i < 4; i++) {
        int c = tid + i * 256;
        float v = (g[c] * (buf[c] - mean) * rstd + b[c]) * mask;
        out[(size_t)row * D + c] = v;
        __half hi, lo; split2(v, hi, lo);
        store_elem(sp, 32, row, c, hi);
        store_elem(sp, 32, row, D + c, lo);
    }
}

// ---------------- attention: 8 q/block, smem-staged K/V, warp softmax ----
#define QT 8
#define KCH 128
#define ATTN_SMEM ((QT*DH + QT*SLEN + KCH*65 + QT) * 4)
__global__ void attn_kernel(const float* __restrict__ qkv, __half* __restrict__ a3) {
    extern __shared__ float sm[];
    float* sq = sm;
    float* sc = sq + QT * DH;
    float* sk = sc + QT * SLEN;
    float* sinv = sk + KCH * 65;
    const int q0 = blockIdx.x * QT, hd = blockIdx.y, bb = blockIdx.z, tid = threadIdx.x;
    const int wid = tid >> 5, lane = tid & 31;
    const int nkb = q0 + QT;
    const size_t rb = (size_t)(bb * SLEN) * K3D + (size_t)hd * DH;

    for (int i = tid; i < QT * DH; i += 128)
        sq[i] = qkv[rb + (size_t)(q0 + i / DH) * K3D + (i % DH)] * 0.125f;
    __syncthreads();

    const float* kb = qkv + rb + D;
    for (int c0 = 0; c0 < nkb; c0 += KCH) {
        int rows = nkb - c0; if (rows > KCH) rows = KCH;
        for (int idx = tid; idx < rows * 16; idx += 128) {
            int r = idx >> 4, c4 = (idx & 15) * 4;
            float4 v = *(const float4*)(kb + (size_t)(c0 + r) * K3D + c4);
            sk[r * 65 + c4 + 0] = v.x; sk[r * 65 + c4 + 1] = v.y;
            sk[r * 65 + c4 + 2] = v.z; sk[r * 65 + c4 + 3] = v.w;
        }
        __syncthreads();
        for (int key = tid; key < rows; key += 128) {
            float a[QT];
            #pragma unroll
            for (int qi = 0; qi < QT; qi++) a[qi] = 0.f;
            #pragma unroll 8
            for (int d = 0; d < DH; d++) {
                float kd = sk[key * 65 + d];
                #pragma unroll
                for (int qi = 0; qi < QT; qi++) a[qi] = fmaf(sq[qi * DH + d], kd, a[qi]);
            }
            #pragma unroll
            for (int qi = 0; qi < QT; qi++) sc[qi * SLEN + c0 + key] = a[qi];
        }
        __syncthreads();
    }

    #pragma unroll
    for (int t = 0; t < 2; t++) {
        int qi = wid * 2 + t, bound = q0 + qi;
        float mx = -1e30f;
        for (int key = lane; key <= bound; key += 32) mx = fmaxf(mx, sc[qi * SLEN + key]);
        #pragma unroll
        for (int o = 16; o; o >>= 1) mx = fmaxf(mx, __shfl_xor_sync(0xffffffffu, mx, o));
        float s = 0.f;
        for (int key = lane; key < nkb; key += 32) {
            float e = (key <= bound) ? expf(sc[qi * SLEN + key] - mx) : 0.f;
            sc[qi * SLEN + key] = e; s += e;
        }
        #pragma unroll
        for (int o = 16; o; o >>= 1) s += __shfl_xor_sync(0xffffffffu, s, o);
        if (lane == 0) sinv[qi] = 1.0f / s;
    }
    __syncthreads();

    const int d = tid & 63, half = tid >> 6;
    const float* vb = qkv + rb + 2 * D;
    float a[QT];
    #pragma unroll
    for (int qi = 0; qi < QT; qi++) a[qi] = 0.f;
    for (int c0 = 0; c0 < nkb; c0 += KCH) {
        int rows = nkb - c0; if (rows > KCH) rows = KCH;
        for (int idx = tid; idx < rows * 16; idx += 128) {
            int r = idx >> 4, c4 = (idx & 15) * 4;
            float4 v = *(const float4*)(vb + (size_t)(c0 + r) * K3D + c4);
            sk[r * 65 + c4 + 0] = v.x; sk[r * 65 + c4 + 1] = v.y;
            sk[r * 65 + c4 + 2] = v.z; sk[r * 65 + c4 + 3] = v.w;
        }
        __syncthreads();
        for (int key = half; key < rows; key += 2) {
            float vv = sk[key * 65 + d];
            #pragma unroll
            for (int qi = 0; qi < QT; qi++)
                a[qi] = fmaf(sc[qi * SLEN + c0 + key], vv, a[qi]);
        }
        __syncthreads();
    }
    for (int qi = 0; qi < QT; qi++) {
        sk[tid] = a[qi]; __syncthreads();
        if (tid < 64) {
            float v = (sk[tid] + sk[tid + 64]) * sinv[qi];
            int row = bb * SLEN + q0 + qi;
            __half hi, lo; split2(v, hi, lo);
            store_elem(a3, 32, row, hd * DH + d, hi);
            store_elem(a3, 32, row, D + hd * DH + d, lo);
        }
        __syncthreads();
    }
}

// ---------------- launcher ----------------
extern "C" void kernel_launch(void* const* d_in, const int* in_sizes, int n_in,
                              void* d_out, int out_size) {
    const int*   x   = (const int*)  d_in[0];
    const int*   len = (const int*)  d_in[1];
    const float* tok = (const float*)d_in[2];
    const float* pos = (const float*)d_in[3];
    const float* leg = (const float*)d_in[4];
    const float* leb = (const float*)d_in[5];
    const float* Wq = (const float*)d_in[6];  const float* bq = (const float*)d_in[7];
    const float* Wk = (const float*)d_in[8];  const float* bk = (const float*)d_in[9];
    const float* Wv = (const float*)d_in[10]; const float* bv = (const float*)d_in[11];
    const float* Wo = (const float*)d_in[12]; const float* bo = (const float*)d_in[13];
    const float* l1g = (const float*)d_in[14]; const float* l1b = (const float*)d_in[15];
    const float* W1 = (const float*)d_in[16]; const float* b1 = (const float*)d_in[17];
    const float* W2 = (const float*)d_in[18]; const float* b2 = (const float*)d_in[19];
    const float* l2g = (const float*)d_in[20]; const float* l2b = (const float*)d_in[21];
    const float* pW = (const float*)d_in[22]; const float* pb = (const float*)d_in[23];
    float* out = (float*)d_out;

    float *h, *qkv, *tmp, *bqkv;
    __half *a3, *s2, *wqkv, *wo, *w1, *w2, *wp;
    cudaGetSymbolAddress((void**)&h, g_h);     cudaGetSymbolAddress((void**)&qkv, g_qkv);
    cudaGetSymbolAddress((void**)&tmp, g_tmp); cudaGetSymbolAddress((void**)&bqkv, g_bqkv);
    cudaGetSymbolAddress((void**)&a3, g_a3);   cudaGetSymbolAddress((void**)&s2, g_s2);
    cudaGetSymbolAddress((void**)&wqkv, g_wqkv); cudaGetSymbolAddress((void**)&wo, g_wo);
    cudaGetSymbolAddress((void**)&w1, g_w1);   cudaGetSymbolAddress((void**)&w2, g_w2);
    cudaGetSymbolAddress((void**)&wp, g_wp);

    const int sm1 = NSTG * 3 * 16384 + 64;   // NB=1: 147520
    const int sm2 = NSTG * 4 * 16384 + 64;   // NB=2: 196672
    cudaFuncSetAttribute(gemm_kernel<1>, cudaFuncAttributeMaxDynamicSharedMemorySize, sm1);
    cudaFuncSetAttribute(gemm_kernel<2>, cudaFuncAttributeMaxDynamicSharedMemorySize, sm2);
    cudaFuncSetAttribute(attn_kernel, cudaFuncAttributeMaxDynamicSharedMemorySize, ATTN_SMEM);

    convert_w<<<dim3(D/32, D/32), 256>>>(Wq, wqkv, D, D, 0);
    convert_w<<<dim3(D/32, D/32), 256>>>(Wk, wqkv, D, D, D);
    convert_w<<<dim3(D/32, D/32), 256>>>(Wv, wqkv, D, D, 2*D);
    concat_bias<<<4, 256>>>(bq, bk, bv, bqkv);
    embed_ln_kernel<<<TOK, 256>>>(x, len, tok, pos, leg, leb, h, a3);
    gemm_kernel<2><<<dim3(TOK/128, K3D/256), 256, sm2>>>(
        a3, wqkv, bqkv, qkv, (__half*)0, D, K3D, 0);

    convert_w<<<dim3(D/32, D/32), 256>>>(Wo, wo, D, D, 0);
    convert_w<<<dim3(D/32, FF/32), 256>>>(W1, w1, D, FF, 0);
    convert_w<<<dim3(FF/32, D/32), 256>>>(W2, w2, FF, D, 0);
    {
        size_t w = (size_t)D * D;
        __half* wq3 = wqkv + (size_t)K3D * D;
        convert_w<<<dim3(D/32, D/32), 256>>>(Wq + w, wq3, D, D, 0);
        convert_w<<<dim3(D/32, D/32), 256>>>(Wk + w, wq3, D, D, D);
        convert_w<<<dim3(D/32, D/32), 256>>>(Wv + w, wq3, D, D, 2*D);
        convert_w<<<dim3(D/32, D/32), 256>>>(Wo + w, wo + (size_t)D*D, D, D, 0);
        convert_w<<<dim3(D/32, FF/32), 256>>>(W1 + (size_t)D*FF, w1 + (size_t)FF*D, D, FF, 0);
        convert_w<<<dim3(FF/32, D/32), 256>>>(W2 + (size_t)FF*D, w2 + (size_t)D*FF, FF, D, 0);
        concat_bias<<<4, 256>>>(bq + D, bk + D, bv + D, bqkv + K3D);
    }
    convert_w<<<dim3(D/32, V/32), 256>>>(pW, wp, D, V, 0);

    for (int i = 0; i < LYRS; i++) {
        if (i > 0)
            gemm_kernel<2><<<dim3(TOK/128, K3D/256), 256, sm2>>>(
                a3, wqkv + (size_t)i*K3D*D, bqkv + (size_t)i*K3D, qkv, (__half*)0, D, K3D, 0);

        attn_kernel<<<dim3(SLEN/QT, H, BS), 128, ATTN_SMEM>>>(qkv, a3);

        gemm_kernel<1><<<dim3(TOK/128, D/128), 128, sm1>>>(
            a3, wo + (size_t)i*D*D, bo + (size_t)i*D, tmp, (__half*)0, D, D, 0);
        add_ln_kernel<<<TOK, 256>>>(h, tmp, l1g + (size_t)i*D, l1b + (size_t)i*D, (const int*)0, h, a3);

        gemm_kernel<2><<<dim3(TOK/128, FF/256), 256, sm2>>>(
            a3, w1 + (size_t)i*FF*D, b1 + (size_t)i*FF, (float*)0, s2, D, FF, 1);

        gemm_kernel<1><<<dim3(TOK/128, D/128), 128, sm1>>>(
            s2, w2 + (size_t)i*D*FF, b2 + (size_t)i*D, tmp, (__half*)0, FF, D, 0);
        add_ln_kernel<<<TOK, 256>>>(h, tmp, l2g + (size_t)i*D, l2b + (size_t)i*D, len, h, a3);
    }

    gemm_kernel<2><<<dim3(TOK/128, V/256), 256, sm2>>>(
        a3, wp, pb, out, (__half*)0, D, V, 0);
}